// round 1
// baseline (speedup 1.0000x reference)
#include <cuda_runtime.h>
#include <math.h>

// Problem constants
#define B_    4
#define NLAT  512
#define NCTX  4096
#define MTOT  (NLAT + NCTX)   // 4608
#define DIM_  512
#define H_    8
#define DH_   64
#define DI_   512             // HEADS * DIM_HEAD
#define KV_LD 1024            // K (512) + V (512) interleaved per row

// Scratch (static device arrays; allocation-free per harness rules)
__device__ float g_Q [(size_t)B_ * NLAT * DI_];          //  4 MB
__device__ float g_KV[(size_t)B_ * MTOT * KV_LD];        // 75.5 MB
__device__ float g_O [(size_t)B_ * NLAT * DI_];          //  4 MB

// ---------------------------------------------------------------------------
// GEMM (NT): C[b, r, c] = sum_k A[b, r, k] * W[c, k]
// A rows may come from two concatenated sources (rows < n1 -> A1, else A2).
// Tile: 128 (rows) x 64 (cols) x 16 (k); 256 threads; 8x4 per thread.
// ---------------------------------------------------------------------------
__global__ __launch_bounds__(256) void gemm_nt(
    const float* __restrict__ A1, size_t a1bs, int n1,
    const float* __restrict__ A2, size_t a2bs,
    const float* __restrict__ W,
    float* __restrict__ C, size_t cbs, int ldc, int K)
{
    __shared__ float As[16][128];
    __shared__ float Bs[16][64];

    const int b       = blockIdx.z;
    const int rowBase = blockIdx.y * 128;
    const int colBase = blockIdx.x * 64;

    const float* A1b = A1 + (size_t)b * a1bs;
    const float* A2b = A2 + (size_t)b * a2bs;
    float*       Cb  = C  + (size_t)b * cbs;

    const int tid = threadIdx.x;
    const int tx  = tid & 15;   // 0..15 -> 4 cols each
    const int ty  = tid >> 4;   // 0..15 -> 8 rows each

    float acc[8][4];
#pragma unroll
    for (int i = 0; i < 8; i++)
#pragma unroll
        for (int j = 0; j < 4; j++) acc[i][j] = 0.f;

    for (int k0 = 0; k0 < K; k0 += 16) {
        // Load A tile (128 x 16) as float4 along k, store transposed As[k][m]
#pragma unroll
        for (int it = 0; it < 2; ++it) {
            int idx = tid + it * 256;      // 0..511
            int row = idx >> 2;            // 0..127
            int kq  = idx & 3;             // which float4 of the 16 k's
            int grow = rowBase + row;
            const float* src = (grow < n1)
                               ? (A1b + (size_t)grow * K)
                               : (A2b + (size_t)(grow - n1) * K);
            float4 v = *(const float4*)(src + k0 + kq * 4);
            As[kq*4+0][row] = v.x; As[kq*4+1][row] = v.y;
            As[kq*4+2][row] = v.z; As[kq*4+3][row] = v.w;
        }
        // Load W tile (64 x 16)
        {
            int col = tid >> 2;            // 0..63
            int kq  = tid & 3;
            float4 v = *(const float4*)(W + (size_t)(colBase + col) * K + k0 + kq * 4);
            Bs[kq*4+0][col] = v.x; Bs[kq*4+1][col] = v.y;
            Bs[kq*4+2][col] = v.z; Bs[kq*4+3][col] = v.w;
        }
        __syncthreads();

#pragma unroll
        for (int kk = 0; kk < 16; ++kk) {
            float4 a0 = *(const float4*)&As[kk][ty * 8];
            float4 a1 = *(const float4*)&As[kk][ty * 8 + 4];
            float4 bv = *(const float4*)&Bs[kk][tx * 4];
            float a[8] = {a0.x, a0.y, a0.z, a0.w, a1.x, a1.y, a1.z, a1.w};
            float bb[4] = {bv.x, bv.y, bv.z, bv.w};
#pragma unroll
            for (int i = 0; i < 8; i++)
#pragma unroll
                for (int j = 0; j < 4; j++)
                    acc[i][j] = fmaf(a[i], bb[j], acc[i][j]);
        }
        __syncthreads();
    }

#pragma unroll
    for (int i = 0; i < 8; i++) {
        float4 v = make_float4(acc[i][0], acc[i][1], acc[i][2], acc[i][3]);
        *(float4*)&Cb[(size_t)(rowBase + ty * 8 + i) * ldc + colBase + tx * 4] = v;
    }
}

// ---------------------------------------------------------------------------
// Fused flash attention (fp32, online softmax).
// Grid: (NLAT/128, H, B). Block: 128 threads.
// Thread t: owns rows r0 = qt*128 + (t>>1) and r1 = r0 + 64, and the
// d-half (t&1)*32 .. +31. Pair lanes (t, t^1) reduce the dot product.
// K/V tiles (64 keys x 64 d) staged in smem with a half-interleaved float4
// layout: group g (d = 4g..4g+3) -> slot (g&7)*2 + (g>>3), so even/odd lanes
// read consecutive float4s (no 32-float bank aliasing).
// ---------------------------------------------------------------------------
__global__ __launch_bounds__(128) void attn_kernel(
    const float* __restrict__ Q, const float* __restrict__ KV,
    float* __restrict__ O)
{
    __shared__ float4 sK[64 * 16];
    __shared__ float4 sV[64 * 16];

    const int qt = blockIdx.x, h = blockIdx.y, b = blockIdx.z;
    const int t    = threadIdx.x;
    const int rp   = t >> 1;
    const int half = t & 1;
    const int r0   = qt * 128 + rp;
    const int r1   = r0 + 64;
    const float scale = 0.125f; // 1/sqrt(64)

    float q0[32], q1[32], acc0[32], acc1[32];
    const float* q0p = Q + ((size_t)(b * NLAT + r0)) * DI_ + h * DH_ + half * 32;
    const float* q1p = Q + ((size_t)(b * NLAT + r1)) * DI_ + h * DH_ + half * 32;
#pragma unroll
    for (int j = 0; j < 32; j++) {
        q0[j] = q0p[j] * scale;
        q1[j] = q1p[j] * scale;
        acc0[j] = 0.f; acc1[j] = 0.f;
    }
    float mx0 = -INFINITY, mx1 = -INFINITY, l0 = 0.f, l1 = 0.f;

    const float* kvb = KV + (size_t)b * MTOT * KV_LD + h * DH_;

    for (int m0 = 0; m0 < MTOT; m0 += 64) {
        const float* kb = kvb + (size_t)m0 * KV_LD;
        // Stage K & V tiles: 64 rows x 16 float4 each; 8 loads/thread/tile
#pragma unroll
        for (int it = 0; it < 8; ++it) {
            int i    = t + it * 128;       // 0..1023
            int row  = i >> 4;
            int g    = i & 15;
            int slot = (g & 7) * 2 + (g >> 3);
            sK[row * 16 + slot] = *(const float4*)(kb + (size_t)row * KV_LD + g * 4);
            sV[row * 16 + slot] = *(const float4*)(kb + (size_t)row * KV_LD + 512 + g * 4);
        }
        __syncthreads();

        for (int mm = 0; mm < 64; ++mm) {
            const float4* kr = sK + mm * 16 + half;
            float s0v[2] = {0.f, 0.f}, s1v[2] = {0.f, 0.f};
#pragma unroll
            for (int jj = 0; jj < 8; jj++) {
                float4 k4 = kr[jj * 2];
                int p = jj & 1;
                s0v[p] = fmaf(q0[jj*4+0], k4.x, s0v[p]);
                s0v[p] = fmaf(q0[jj*4+1], k4.y, s0v[p]);
                s0v[p] = fmaf(q0[jj*4+2], k4.z, s0v[p]);
                s0v[p] = fmaf(q0[jj*4+3], k4.w, s0v[p]);
                s1v[p] = fmaf(q1[jj*4+0], k4.x, s1v[p]);
                s1v[p] = fmaf(q1[jj*4+1], k4.y, s1v[p]);
                s1v[p] = fmaf(q1[jj*4+2], k4.z, s1v[p]);
                s1v[p] = fmaf(q1[jj*4+3], k4.w, s1v[p]);
            }
            float s0 = s0v[0] + s0v[1];
            float s1 = s1v[0] + s1v[1];
            s0 += __shfl_xor_sync(0xffffffffu, s0, 1);
            s1 += __shfl_xor_sync(0xffffffffu, s1, 1);

            float p0, p1;
            if (s0 > mx0) {                      // rare: ~log(M) times per row
                float c = __expf(mx0 - s0);
                mx0 = s0; l0 *= c; p0 = 1.f;
#pragma unroll
                for (int j = 0; j < 32; j++) acc0[j] *= c;
            } else {
                p0 = __expf(s0 - mx0);
            }
            l0 += p0;
            if (s1 > mx1) {
                float c = __expf(mx1 - s1);
                mx1 = s1; l1 *= c; p1 = 1.f;
#pragma unroll
                for (int j = 0; j < 32; j++) acc1[j] *= c;
            } else {
                p1 = __expf(s1 - mx1);
            }
            l1 += p1;

            const float4* vr = sV + mm * 16 + half;
#pragma unroll
            for (int jj = 0; jj < 8; jj++) {
                float4 v4 = vr[jj * 2];
                acc0[jj*4+0] = fmaf(p0, v4.x, acc0[jj*4+0]);
                acc0[jj*4+1] = fmaf(p0, v4.y, acc0[jj*4+1]);
                acc0[jj*4+2] = fmaf(p0, v4.z, acc0[jj*4+2]);
                acc0[jj*4+3] = fmaf(p0, v4.w, acc0[jj*4+3]);
                acc1[jj*4+0] = fmaf(p1, v4.x, acc1[jj*4+0]);
                acc1[jj*4+1] = fmaf(p1, v4.y, acc1[jj*4+1]);
                acc1[jj*4+2] = fmaf(p1, v4.z, acc1[jj*4+2]);
                acc1[jj*4+3] = fmaf(p1, v4.w, acc1[jj*4+3]);
            }
        }
        __syncthreads();
    }

    const float i0 = 1.f / l0, i1 = 1.f / l1;
    float* o0 = O + ((size_t)(b * NLAT + r0)) * DI_ + h * DH_ + half * 32;
    float* o1 = O + ((size_t)(b * NLAT + r1)) * DI_ + h * DH_ + half * 32;
#pragma unroll
    for (int jj = 0; jj < 8; jj++) {
        *(float4*)(o0 + jj * 4) = make_float4(acc0[jj*4+0]*i0, acc0[jj*4+1]*i0,
                                              acc0[jj*4+2]*i0, acc0[jj*4+3]*i0);
        *(float4*)(o1 + jj * 4) = make_float4(acc1[jj*4+0]*i1, acc1[jj*4+1]*i1,
                                              acc1[jj*4+2]*i1, acc1[jj*4+3]*i1);
    }
}

// ---------------------------------------------------------------------------
// Launch: Q-proj -> KV-proj (concat handled in-GEMM) -> flash attention -> out-proj
// Inputs per metadata order: x, context, Wq, Wkv, Wout. Output fp32 [4,512,512].
// ---------------------------------------------------------------------------
extern "C" void kernel_launch(void* const* d_in, const int* in_sizes, int n_in,
                              void* d_out, int out_size)
{
    const float* x    = (const float*)d_in[0];
    const float* ctx  = (const float*)d_in[1];
    const float* Wq   = (const float*)d_in[2];
    const float* Wkv  = (const float*)d_in[3];
    const float* Wout = (const float*)d_in[4];
    float* out = (float*)d_out;

    float *pQ, *pKV, *pO;
    cudaGetSymbolAddress((void**)&pQ,  g_Q);
    cudaGetSymbolAddress((void**)&pKV, g_KV);
    cudaGetSymbolAddress((void**)&pO,  g_O);

    // Q = x @ Wq^T                          (512 x 512 x 512, per batch)
    gemm_nt<<<dim3(DI_ / 64, NLAT / 128, B_), 256>>>(
        x, (size_t)NLAT * DIM_, NLAT, x, 0, Wq,
        pQ, (size_t)NLAT * DI_, DI_, DIM_);

    // KV = concat(x, context) @ Wkv^T       (4608 x 1024 x 512, per batch)
    gemm_nt<<<dim3(KV_LD / 64, MTOT / 128, B_), 256>>>(
        x, (size_t)NLAT * DIM_, NLAT, ctx, (size_t)NCTX * DIM_, Wkv,
        pKV, (size_t)MTOT * KV_LD, KV_LD, DIM_);

    // O = softmax(Q K^T / sqrt(d)) V        (fused, per (b, h, q-tile))
    attn_kernel<<<dim3(NLAT / 128, H_, B_), 128>>>(pQ, pKV, pO);

    // out = O @ Wout^T                      (512 x 512 x 512, per batch)
    gemm_nt<<<dim3(DIM_ / 64, NLAT / 128, B_), 256>>>(
        pO, (size_t)NLAT * DI_, NLAT, pO, 0, Wout,
        out, (size_t)NLAT * DIM_, DIM_, DI_);
}

// round 3
// speedup vs baseline: 3.7313x; 3.7313x over previous
#include <cuda_runtime.h>
#include <math.h>
#include <cstdint>

// Problem constants
#define B_    4
#define NLAT  512
#define NCTX  4096
#define MTOT  4608
#define DIM_  512
#define H_    8
#define DH_   64
#define DI_   512
#define KV_LD 1024            // K (512) | V (512) per row

// Scratch (allocation-free per harness rules)
__device__ float g_Q [(size_t)B_ * NLAT * DI_];
__device__ float g_KV[(size_t)B_ * MTOT * KV_LD];
__device__ float g_O [(size_t)B_ * NLAT * DI_];

// ---------------------------------------------------------------------------
// tf32 helpers (baseline sm_80+ ISA — assembles under compute_103)
// ---------------------------------------------------------------------------
__device__ __forceinline__ uint32_t f2t(float f) {
    uint32_t r;
    asm("cvt.rna.tf32.f32 %0, %1;" : "=r"(r) : "f"(f));
    return r;
}

// D += A(m16k8) * B(k8n8), tf32 in, f32 accum. C/D in-place.
#define MMA_TF32(C, A0, A1, A2, A3, B0, B1) \
    asm volatile("mma.sync.aligned.m16n8k8.row.col.f32.tf32.tf32.f32 " \
        "{%0,%1,%2,%3}, {%4,%5,%6,%7}, {%8,%9}, {%0,%1,%2,%3};" \
        : "+f"((C)[0]), "+f"((C)[1]), "+f"((C)[2]), "+f"((C)[3]) \
        : "r"(A0), "r"(A1), "r"(A2), "r"(A3), "r"(B0), "r"(B1))

// ===========================================================================
// Tensor-core GEMM (NT): C[b,r,c] = sum_k A[b,r,k] * W[c,k]
// CTA 128x128, 8 warps (each 64x32), K-tile 32, double-buffered swizzled smem.
// A rows < n1 from A1 else A2 (handles concat(x, ctx)).
// smem word layout: tile[row][col ^ ((row&7)<<2)], row stride 32 floats.
// ===========================================================================
#define GEMM_SMEM (2 * 8192 * 4)   // 2 bufs x (A 4096 + B 4096 words) = 64KB

__global__ __launch_bounds__(256) void gemm_mma(
    const float* __restrict__ A1, size_t a1bs, int n1,
    const float* __restrict__ A2, size_t a2bs,
    const float* __restrict__ W,
    float* __restrict__ C, size_t cbs, int ldc, int K)
{
    extern __shared__ uint32_t sm[];

    const int tid = threadIdx.x, w = tid >> 5, lane = tid & 31;
    const int g = lane >> 2, kq = lane & 3;
    const int b = blockIdx.z;
    const int rowBase = blockIdx.y * 128, colBase = blockIdx.x * 128;
    const int wm = (w >> 2) * 64, wn = (w & 3) * 32;

    const float* A1b = A1 + (size_t)b * a1bs;
    const float* A2b = A2 + (size_t)b * a2bs;
    float*       Cb  = C  + (size_t)b * cbs;

    float c[4][4][4];
#pragma unroll
    for (int mt = 0; mt < 4; mt++)
#pragma unroll
        for (int nt = 0; nt < 4; nt++)
#pragma unroll
            for (int j = 0; j < 4; j++) c[mt][nt][j] = 0.f;

    // Staging: thread -> row sr (0..127), col half sc0 (0 or 16)
    const int sr  = tid >> 1;
    const int sc0 = (tid & 1) * 16;
    const int grow = rowBase + sr;
    const float* srcA = (grow < n1) ? (A1b + (size_t)grow * K)
                                    : (A2b + (size_t)(grow - n1) * K);
    const float* srcW = W + (size_t)(colBase + sr) * K;

    float4 ar[4], br[4];
    auto ldgTile = [&](int k0) {
#pragma unroll
        for (int i = 0; i < 4; i++) {
            ar[i] = *(const float4*)(srcA + k0 + sc0 + 4 * i);
            br[i] = *(const float4*)(srcW + k0 + sc0 + 4 * i);
        }
    };
    auto stsTile = [&](int buf) {
        uint32_t* sA = sm + buf * 8192;
        uint32_t* sB = sA + 4096;
        const int sw = (sr & 7) << 2;
#pragma unroll
        for (int i = 0; i < 4; i++) {
            int idx = sr * 32 + ((sc0 + 4 * i) ^ sw);
            uint4 va = make_uint4(f2t(ar[i].x), f2t(ar[i].y), f2t(ar[i].z), f2t(ar[i].w));
            uint4 vb = make_uint4(f2t(br[i].x), f2t(br[i].y), f2t(br[i].z), f2t(br[i].w));
            *(uint4*)&sA[idx] = va;
            *(uint4*)&sB[idx] = vb;
        }
    };

    ldgTile(0);
    stsTile(0);
    __syncthreads();

    const int KT = K >> 5;   // k-tiles of 32
    for (int kt = 0; kt < KT; ++kt) {
        if (kt + 1 < KT) ldgTile((kt + 1) * 32);

        uint32_t* sA = sm + (kt & 1) * 8192;
        uint32_t* sB = sA + 4096;
#pragma unroll
        for (int ks = 0; ks < 4; ++ks) {
            uint32_t a[4][4], bf[4][2];
            const int colw = (ks * 8 + kq) ^ (g << 2);
#pragma unroll
            for (int mt = 0; mt < 4; mt++) {
                int r0 = wm + mt * 16 + g;
                int i0 = r0 * 32 + colw, i1 = (r0 + 8) * 32 + colw;
                a[mt][0] = sA[i0];     a[mt][1] = sA[i1];
                a[mt][2] = sA[i0 ^ 4]; a[mt][3] = sA[i1 ^ 4];
            }
#pragma unroll
            for (int nt = 0; nt < 4; nt++) {
                int r = wn + nt * 8 + g;
                int i0 = r * 32 + colw;
                bf[nt][0] = sB[i0]; bf[nt][1] = sB[i0 ^ 4];
            }
#pragma unroll
            for (int mt = 0; mt < 4; mt++)
#pragma unroll
                for (int nt = 0; nt < 4; nt++)
                    MMA_TF32(c[mt][nt], a[mt][0], a[mt][1], a[mt][2], a[mt][3],
                             bf[nt][0], bf[nt][1]);
        }
        if (kt + 1 < KT) {
            stsTile((kt + 1) & 1);
            __syncthreads();
        }
    }

    // Epilogue: direct float2 stores from C-layout fragments
#pragma unroll
    for (int mt = 0; mt < 4; mt++) {
        int row0 = rowBase + wm + mt * 16 + g;
#pragma unroll
        for (int nt = 0; nt < 4; nt++) {
            int col = colBase + wn + nt * 8 + 2 * kq;
            *(float2*)&Cb[(size_t)row0 * ldc + col] =
                make_float2(c[mt][nt][0], c[mt][nt][1]);
            *(float2*)&Cb[(size_t)(row0 + 8) * ldc + col] =
                make_float2(c[mt][nt][2], c[mt][nt][3]);
        }
    }
}

// ===========================================================================
// Tensor-core flash attention. Grid (4, H, B), 256 threads (8 warps).
// Warp w owns q-rows [qt*128 + w*16, +16). Q fragments live in registers.
// K smem: sK[key][d ^ ((key&7)<<2)], V smem transposed:
// sV[d][key ^ (((d&7)^((d>>3)&7))<<2)]. Both conflict-free for frag reads.
// P (C-layout) -> A-fragment via intra-quad shuffles (no smem round trip).
// ===========================================================================
#define ATT_SMEM (2 * 8192 * 4)   // 2 bufs x (K 4096 + V 4096 words) = 64KB

__global__ __launch_bounds__(256) void attn_mma(
    const float* __restrict__ Q, const float* __restrict__ KV,
    float* __restrict__ O)
{
    extern __shared__ uint32_t sm[];

    const int qt = blockIdx.x, h = blockIdx.y, b = blockIdx.z;
    const int tid = threadIdx.x, w = tid >> 5, lane = tid & 31;
    const int g = lane >> 2, kq = lane & 3;

    // --- Q fragments (scaled by 1/8, rna-rounded to tf32), register-resident
    uint32_t qf[8][4];
    {
        const float* q0 = Q + (size_t)(b * NLAT + qt * 128 + w * 16 + g) * DI_ + h * DH_;
        const float* q1 = q0 + 8 * DI_;
#pragma unroll
        for (int s = 0; s < 8; s++) {
            qf[s][0] = f2t(q0[8 * s + kq]     * 0.125f);
            qf[s][1] = f2t(q1[8 * s + kq]     * 0.125f);
            qf[s][2] = f2t(q0[8 * s + kq + 4] * 0.125f);
            qf[s][3] = f2t(q1[8 * s + kq + 4] * 0.125f);
        }
    }

    float o[8][4];
#pragma unroll
    for (int dt = 0; dt < 8; dt++)
#pragma unroll
        for (int j = 0; j < 4; j++) o[dt][j] = 0.f;
    float mA = -INFINITY, mB = -INFINITY, lA = 0.f, lB = 0.f;

    // --- staging: thread -> key row sRow (0..63), d-chunk sC0 (0/16/32/48)
    const float* kvB = KV + (size_t)b * MTOT * KV_LD + h * DH_;
    const int sRow = tid >> 2, sC0 = (tid & 3) * 16;

    float4 kr[4], vr[4];
    auto ldgTile = [&](int m0) {
        const float* kp = kvB + (size_t)(m0 + sRow) * KV_LD + sC0;
#pragma unroll
        for (int i = 0; i < 4; i++) {
            kr[i] = *(const float4*)(kp + 4 * i);
            vr[i] = *(const float4*)(kp + 512 + 4 * i);
        }
    };
    auto stsTile = [&](int buf) {
        uint32_t* sK = sm + buf * 8192;
        uint32_t* sV = sK + 4096;
        const int sw = (sRow & 7) << 2;
#pragma unroll
        for (int i = 0; i < 4; i++) {
            int idx = sRow * 64 + ((sC0 + 4 * i) ^ sw);
            *(uint4*)&sK[idx] = make_uint4(f2t(kr[i].x), f2t(kr[i].y),
                                           f2t(kr[i].z), f2t(kr[i].w));
        }
#pragma unroll
        for (int i = 0; i < 4; i++) {
            float vv[4] = {vr[i].x, vr[i].y, vr[i].z, vr[i].w};
#pragma unroll
            for (int e = 0; e < 4; e++) {
                int d = sC0 + 4 * i + e;
                int vsw = (((d & 7) ^ ((d >> 3) & 7)) << 2);
                sV[d * 64 + (sRow ^ vsw)] = f2t(vv[e]);
            }
        }
    };

    ldgTile(0);
    stsTile(0);
    __syncthreads();

    const int NT = MTOT / 64;   // 72 key tiles
    for (int t = 0; t < NT; ++t) {
        if (t + 1 < NT) ldgTile((t + 1) * 64);

        uint32_t* sK = sm + (t & 1) * 8192;
        uint32_t* sV = sK + 4096;

        // ---- S = Q K^T (per warp: 16 x 64)
        float s[8][4];
#pragma unroll
        for (int nt = 0; nt < 8; nt++)
#pragma unroll
            for (int j = 0; j < 4; j++) s[nt][j] = 0.f;
#pragma unroll
        for (int ks = 0; ks < 8; ks++) {
            const int colw = (8 * ks + kq) ^ (g << 2);
#pragma unroll
            for (int nt = 0; nt < 8; nt++) {
                int idx = (8 * nt + g) * 64 + colw;
                MMA_TF32(s[nt], qf[ks][0], qf[ks][1], qf[ks][2], qf[ks][3],
                         sK[idx], sK[idx ^ 4]);
            }
        }

        // ---- online softmax (rows g and g+8 of this warp's 16)
        float tA = -INFINITY, tB = -INFINITY;
#pragma unroll
        for (int nt = 0; nt < 8; nt++) {
            tA = fmaxf(tA, fmaxf(s[nt][0], s[nt][1]));
            tB = fmaxf(tB, fmaxf(s[nt][2], s[nt][3]));
        }
        tA = fmaxf(tA, __shfl_xor_sync(0xffffffffu, tA, 1));
        tA = fmaxf(tA, __shfl_xor_sync(0xffffffffu, tA, 2));
        tB = fmaxf(tB, __shfl_xor_sync(0xffffffffu, tB, 1));
        tB = fmaxf(tB, __shfl_xor_sync(0xffffffffu, tB, 2));

        float mnA = fmaxf(mA, tA), mnB = fmaxf(mB, tB);
        float scA = __expf(mA - mnA), scB = __expf(mB - mnB);
        mA = mnA; mB = mnB;

        float suA = 0.f, suB = 0.f;
#pragma unroll
        for (int nt = 0; nt < 8; nt++) {
            s[nt][0] = __expf(s[nt][0] - mnA); suA += s[nt][0];
            s[nt][1] = __expf(s[nt][1] - mnA); suA += s[nt][1];
            s[nt][2] = __expf(s[nt][2] - mnB); suB += s[nt][2];
            s[nt][3] = __expf(s[nt][3] - mnB); suB += s[nt][3];
        }
        suA += __shfl_xor_sync(0xffffffffu, suA, 1);
        suA += __shfl_xor_sync(0xffffffffu, suA, 2);
        suB += __shfl_xor_sync(0xffffffffu, suB, 1);
        suB += __shfl_xor_sync(0xffffffffu, suB, 2);
        lA = lA * scA + suA;
        lB = lB * scB + suB;
#pragma unroll
        for (int dt = 0; dt < 8; dt++) {
            o[dt][0] *= scA; o[dt][1] *= scA;
            o[dt][2] *= scB; o[dt][3] *= scB;
        }

        // ---- O += P V  (A-fragment built from C-layout P via quad shuffles)
        const int src  = (lane & ~3) | (kq >> 1);
        const int src2 = src | 2;
        const int odd  = kq & 1;
#pragma unroll
        for (int ks = 0; ks < 8; ks++) {
            float f00 = __shfl_sync(0xffffffffu, s[ks][0], src);
            float f01 = __shfl_sync(0xffffffffu, s[ks][1], src);
            float f20 = __shfl_sync(0xffffffffu, s[ks][2], src);
            float f21 = __shfl_sync(0xffffffffu, s[ks][3], src);
            float h00 = __shfl_sync(0xffffffffu, s[ks][0], src2);
            float h01 = __shfl_sync(0xffffffffu, s[ks][1], src2);
            float h20 = __shfl_sync(0xffffffffu, s[ks][2], src2);
            float h21 = __shfl_sync(0xffffffffu, s[ks][3], src2);
            uint32_t a0 = __float_as_uint(odd ? f01 : f00);
            uint32_t a1 = __float_as_uint(odd ? f21 : f20);
            uint32_t a2 = __float_as_uint(odd ? h01 : h00);
            uint32_t a3 = __float_as_uint(odd ? h21 : h20);
#pragma unroll
            for (int dt = 0; dt < 8; dt++) {
                int idx = (8 * dt + g) * 64 + ((8 * ks + kq) ^ ((g ^ dt) << 2));
                MMA_TF32(o[dt], a0, a1, a2, a3, sV[idx], sV[idx ^ 4]);
            }
        }

        if (t + 1 < NT) {
            stsTile((t + 1) & 1);
            __syncthreads();
        }
    }

    // ---- normalize + store
    const float rA = 1.f / lA, rB = 1.f / lB;
    float* oP = O + (size_t)(b * NLAT + qt * 128 + w * 16 + g) * DI_ + h * DH_;
#pragma unroll
    for (int dt = 0; dt < 8; dt++) {
        *(float2*)&oP[8 * dt + 2 * kq] =
            make_float2(o[dt][0] * rA, o[dt][1] * rA);
        *(float2*)&oP[8 * DI_ + 8 * dt + 2 * kq] =
            make_float2(o[dt][2] * rB, o[dt][3] * rB);
    }
}

// ===========================================================================
// fp32 SIMT GEMM (out-proj only: keeps final output at full fp32 precision)
// ===========================================================================
__global__ __launch_bounds__(256) void gemm_nt(
    const float* __restrict__ A, const float* __restrict__ W,
    float* __restrict__ C, int K)
{
    __shared__ float As[16][128];
    __shared__ float Bs[16][64];

    const int b       = blockIdx.z;
    const int rowBase = blockIdx.y * 128;
    const int colBase = blockIdx.x * 64;
    const float* Ab = A + (size_t)b * NLAT * DI_;
    float*       Cb = C + (size_t)b * NLAT * DIM_;

    const int tid = threadIdx.x;
    const int tx  = tid & 15, ty = tid >> 4;

    float acc[8][4];
#pragma unroll
    for (int i = 0; i < 8; i++)
#pragma unroll
        for (int j = 0; j < 4; j++) acc[i][j] = 0.f;

    for (int k0 = 0; k0 < K; k0 += 16) {
#pragma unroll
        for (int it = 0; it < 2; ++it) {
            int idx = tid + it * 256;
            int row = idx >> 2, kg = idx & 3;
            float4 v = *(const float4*)(Ab + (size_t)(rowBase + row) * K + k0 + kg * 4);
            As[kg*4+0][row] = v.x; As[kg*4+1][row] = v.y;
            As[kg*4+2][row] = v.z; As[kg*4+3][row] = v.w;
        }
        {
            int col = tid >> 2, kg = tid & 3;
            float4 v = *(const float4*)(W + (size_t)(colBase + col) * K + k0 + kg * 4);
            Bs[kg*4+0][col] = v.x; Bs[kg*4+1][col] = v.y;
            Bs[kg*4+2][col] = v.z; Bs[kg*4+3][col] = v.w;
        }
        __syncthreads();
#pragma unroll
        for (int kk = 0; kk < 16; ++kk) {
            float4 a0 = *(const float4*)&As[kk][ty * 8];
            float4 a1 = *(const float4*)&As[kk][ty * 8 + 4];
            float4 bv = *(const float4*)&Bs[kk][tx * 4];
            float a[8] = {a0.x, a0.y, a0.z, a0.w, a1.x, a1.y, a1.z, a1.w};
            float bb[4] = {bv.x, bv.y, bv.z, bv.w};
#pragma unroll
            for (int i = 0; i < 8; i++)
#pragma unroll
                for (int j = 0; j < 4; j++)
                    acc[i][j] = fmaf(a[i], bb[j], acc[i][j]);
        }
        __syncthreads();
    }
#pragma unroll
    for (int i = 0; i < 8; i++) {
        *(float4*)&Cb[(size_t)(rowBase + ty * 8 + i) * DIM_ + colBase + tx * 4] =
            make_float4(acc[i][0], acc[i][1], acc[i][2], acc[i][3]);
    }
}

// ===========================================================================
// Launch
// ===========================================================================
extern "C" void kernel_launch(void* const* d_in, const int* in_sizes, int n_in,
                              void* d_out, int out_size)
{
    const float* x    = (const float*)d_in[0];
    const float* ctx  = (const float*)d_in[1];
    const float* Wq   = (const float*)d_in[2];
    const float* Wkv  = (const float*)d_in[3];
    const float* Wout = (const float*)d_in[4];
    float* out = (float*)d_out;

    float *pQ, *pKV, *pO;
    cudaGetSymbolAddress((void**)&pQ,  g_Q);
    cudaGetSymbolAddress((void**)&pKV, g_KV);
    cudaGetSymbolAddress((void**)&pO,  g_O);

    cudaFuncSetAttribute(gemm_mma, cudaFuncAttributeMaxDynamicSharedMemorySize, GEMM_SMEM);
    cudaFuncSetAttribute(attn_mma, cudaFuncAttributeMaxDynamicSharedMemorySize, ATT_SMEM);

    // Q = x @ Wq^T                       (tf32 mma)
    gemm_mma<<<dim3(DI_ / 128, NLAT / 128, B_), 256, GEMM_SMEM>>>(
        x, (size_t)NLAT * DIM_, NLAT, x, 0, Wq,
        pQ, (size_t)NLAT * DI_, DI_, DIM_);

    // KV = concat(x, ctx) @ Wkv^T        (tf32 mma)
    gemm_mma<<<dim3(KV_LD / 128, MTOT / 128, B_), 256, GEMM_SMEM>>>(
        x, (size_t)NLAT * DIM_, NLAT, ctx, (size_t)NCTX * DIM_, Wkv,
        pKV, (size_t)MTOT * KV_LD, KV_LD, DIM_);

    // O = softmax(Q K^T / 8) V           (tf32 mma flash)
    attn_mma<<<dim3(NLAT / 128, H_, B_), 256, ATT_SMEM>>>(pQ, pKV, pO);

    // out = O @ Wout^T                   (fp32 SIMT for final precision)
    gemm_nt<<<dim3(DIM_ / 64, NLAT / 128, B_), 256>>>(pO, Wout, out, DI_);
}

// round 4
// speedup vs baseline: 5.4927x; 1.4721x over previous
#include <cuda_runtime.h>
#include <math.h>
#include <cstdint>

// Problem constants
#define B_    4
#define NLAT  512
#define NCTX  4096
#define MTOT  4608
#define DIM_  512
#define H_    8
#define DH_   64
#define DI_   512
#define KV_LD 1024            // K (512) | V (512) per row
#define SPLIT 4
#define SEGK  (MTOT / SPLIT)  // 1152 keys per split
#define NT_   (SEGK / 64)     // 18 tiles per split

// Scratch (allocation-free per harness rules)
__device__ float g_xt  [(size_t)B_ * NLAT * DIM_];
__device__ float g_ctxt[(size_t)B_ * NCTX * DIM_];
__device__ float g_wqt [(size_t)DI_ * DIM_];
__device__ float g_wkvt[(size_t)2 * DI_ * DIM_];
__device__ float g_Q   [(size_t)B_ * NLAT * DI_];
__device__ float g_KV  [(size_t)B_ * MTOT * KV_LD];
__device__ float g_O   [(size_t)B_ * NLAT * DI_];
__device__ float g_PO  [(size_t)B_ * H_ * 4 * SPLIT * 128 * 64];
__device__ float g_PM  [(size_t)B_ * H_ * 4 * SPLIT * 128];
__device__ float g_PL  [(size_t)B_ * H_ * 4 * SPLIT * 128];

// ---------------------------------------------------------------------------
// Helpers
// ---------------------------------------------------------------------------
__device__ __forceinline__ uint32_t f2t(float f) {
    uint32_t r;
    asm("cvt.rna.tf32.f32 %0, %1;" : "=r"(r) : "f"(f));
    return r;
}
__device__ __forceinline__ uint32_t smem_u32(const void* p) {
    uint32_t a;
    asm("{ .reg .u64 t; cvta.to.shared.u64 t, %1; cvt.u32.u64 %0, t; }"
        : "=r"(a) : "l"(p));
    return a;
}
__device__ __forceinline__ void cpa16(uint32_t dst, const void* src) {
    asm volatile("cp.async.cg.shared.global [%0], [%1], 16;" :: "r"(dst), "l"(src));
}
#define CPA_COMMIT() asm volatile("cp.async.commit_group;" ::: "memory")
#define CPA_WAIT(n)  asm volatile("cp.async.wait_group %0;" :: "n"(n) : "memory")

#define MMA_TF32(C, A0, A1, A2, A3, B0, B1) \
    asm volatile("mma.sync.aligned.m16n8k8.row.col.f32.tf32.tf32.f32 " \
        "{%0,%1,%2,%3}, {%4,%5,%6,%7}, {%8,%9}, {%0,%1,%2,%3};" \
        : "+f"((C)[0]), "+f"((C)[1]), "+f"((C)[2]), "+f"((C)[3]) \
        : "r"(A0), "r"(A1), "r"(A2), "r"(A3), "r"(B0), "r"(B1))

// ===========================================================================
// Prep: round inputs to tf32 once (Wq also folded with 0.125 * log2(e)).
// Pre-rounded values pass losslessly through mma's tf32 operand truncation.
// ===========================================================================
__global__ __launch_bounds__(256) void prep_round(
    const float* __restrict__ x, const float* __restrict__ ctx,
    const float* __restrict__ Wq, const float* __restrict__ Wkv,
    float* __restrict__ xt, float* __restrict__ ctxt,
    float* __restrict__ wqt, float* __restrict__ wkvt)
{
    const size_t nx = (size_t)B_ * NLAT * DIM_ / 4;
    const size_t nc = (size_t)B_ * NCTX * DIM_ / 4;
    const size_t nq = (size_t)DI_ * DIM_ / 4;
    const size_t nk = (size_t)2 * DI_ * DIM_ / 4;
    size_t i = (size_t)blockIdx.x * 256 + threadIdx.x;

    const float* src; float* dst; float s = 1.f;
    if (i < nx)                { src = x;   dst = xt; }
    else if ((i -= nx) < nc)   { src = ctx; dst = ctxt; }
    else if ((i -= nc) < nq)   { src = Wq;  dst = wqt; s = 0.18033688011112042f; }
    else if ((i -= nq) < nk)   { src = Wkv; dst = wkvt; }
    else return;

    float4 v = *(const float4*)(src + 4 * i);
    float4 o;
    o.x = __uint_as_float(f2t(v.x * s));
    o.y = __uint_as_float(f2t(v.y * s));
    o.z = __uint_as_float(f2t(v.z * s));
    o.w = __uint_as_float(f2t(v.w * s));
    *(float4*)(dst + 4 * i) = o;
}

// ===========================================================================
// cp.async tf32 GEMM (NT): C[b,r,c] = sum_k A[b,r,k] * W[c,k]
// CTA 128x128, 8 warps (64x32 each), K-tile 32, 3-stage cp.async pipeline.
// Inputs already tf32-rounded. Output optionally re-rounded to tf32.
// smem layout (per stage): A/B tile word = row*32 + (colword ^ ((row&7)<<2)).
// ===========================================================================
#define GEMM_SMEM (3 * 8192 * 4)   // 3 stages x (A 4096 + B 4096 words) = 96KB

__global__ void __launch_bounds__(256, 2) gemm_ca(
    const float* __restrict__ A1, size_t a1bs, int n1,
    const float* __restrict__ A2, size_t a2bs,
    const float* __restrict__ W,
    float* __restrict__ C, size_t cbs, int ldc, int K, int roundOut)
{
    extern __shared__ uint32_t sm[];
    const uint32_t smb = smem_u32(sm);

    const int tid = threadIdx.x, w = tid >> 5, lane = tid & 31;
    const int g = lane >> 2, kq = lane & 3;
    const int b = blockIdx.z;
    const int rowBase = blockIdx.y * 128, colBase = blockIdx.x * 128;
    const int wm = (w >> 2) * 64, wn = (w & 3) * 32;

    const float* A1b = A1 + (size_t)b * a1bs;
    const float* A2b = A2 + (size_t)b * a2bs;
    float*       Cb  = C  + (size_t)b * cbs;

    float c[4][4][4];
#pragma unroll
    for (int mt = 0; mt < 4; mt++)
#pragma unroll
        for (int nt = 0; nt < 4; nt++)
#pragma unroll
            for (int j = 0; j < 4; j++) c[mt][nt][j] = 0.f;

    auto issue = [&](int kt, int stage) {
        const int k0 = kt * 32;
        const uint32_t base = smb + stage * 8192 * 4;
#pragma unroll
        for (int i = 0; i < 4; i++) {
            int idx = tid + i * 256;        // 0..1023
            int r = idx >> 3, ch = idx & 7; // row, 16B chunk (4 words)
            int grow = rowBase + r;
            const float* srcA = ((grow < n1) ? (A1b + (size_t)grow * K)
                                             : (A2b + (size_t)(grow - n1) * K)) + k0 + ch * 4;
            uint32_t dA = base + (uint32_t)((r * 32 + ((ch * 4) ^ ((r & 7) << 2))) << 2);
            cpa16(dA, srcA);
            const float* srcB = W + (size_t)(colBase + r) * K + k0 + ch * 4;
            cpa16(dA + 4096 * 4, srcB);
        }
    };

    issue(0, 0); CPA_COMMIT();
    issue(1, 1); CPA_COMMIT();

    const int KT = K >> 5;   // 16
    for (int kt = 0; kt < KT; ++kt) {
        if (kt == KT - 1) { CPA_WAIT(0); } else { CPA_WAIT(1); }
        __syncthreads();
        if (kt + 2 < KT) { issue(kt + 2, (kt + 2) % 3); CPA_COMMIT(); }

        const uint32_t* sA = sm + (kt % 3) * 8192;
        const uint32_t* sB = sA + 4096;
#pragma unroll
        for (int ks = 0; ks < 4; ++ks) {
            uint32_t a[4][4], bf[4][2];
            const int colw = (ks * 8 + kq) ^ (g << 2);
#pragma unroll
            for (int mt = 0; mt < 4; mt++) {
                int r0 = wm + mt * 16 + g;
                int i0 = r0 * 32 + colw, i1 = (r0 + 8) * 32 + colw;
                a[mt][0] = sA[i0];     a[mt][1] = sA[i1];
                a[mt][2] = sA[i0 ^ 4]; a[mt][3] = sA[i1 ^ 4];
            }
#pragma unroll
            for (int nt = 0; nt < 4; nt++) {
                int i0 = (wn + nt * 8 + g) * 32 + colw;
                bf[nt][0] = sB[i0]; bf[nt][1] = sB[i0 ^ 4];
            }
#pragma unroll
            for (int mt = 0; mt < 4; mt++)
#pragma unroll
                for (int nt = 0; nt < 4; nt++)
                    MMA_TF32(c[mt][nt], a[mt][0], a[mt][1], a[mt][2], a[mt][3],
                             bf[nt][0], bf[nt][1]);
        }
    }

#pragma unroll
    for (int mt = 0; mt < 4; mt++) {
        int row0 = rowBase + wm + mt * 16 + g;
#pragma unroll
        for (int nt = 0; nt < 4; nt++) {
            int col = colBase + wn + nt * 8 + 2 * kq;
            float v0 = c[mt][nt][0], v1 = c[mt][nt][1];
            float v2 = c[mt][nt][2], v3 = c[mt][nt][3];
            if (roundOut) {
                v0 = __uint_as_float(f2t(v0)); v1 = __uint_as_float(f2t(v1));
                v2 = __uint_as_float(f2t(v2)); v3 = __uint_as_float(f2t(v3));
            }
            *(float2*)&Cb[(size_t)row0 * ldc + col]       = make_float2(v0, v1);
            *(float2*)&Cb[(size_t)(row0 + 8) * ldc + col] = make_float2(v2, v3);
        }
    }
}

// ===========================================================================
// Flash attention, split-K by 4, cp.async 2-stage, tf32 mma.
// Grid (4, H, B*SPLIT), 256 threads. Q/K/V already tf32-rounded, Q pre-scaled
// by 0.125*log2(e) (softmax runs in exp2 domain).
// smem: K rows padded to 76 words, V rows (row-major!) padded to 72 words —
// both B-fragment read patterns bank-conflict-free.
// Emits unnormalized partials + per-row (m, l) for the merge pass.
// ===========================================================================
#define KPAD 76
#define VPAD 72
#define STG_W (64 * KPAD + 64 * VPAD)      // 9472 words per stage
#define ATT_SMEM (2 * STG_W * 4)           // 75776 B

__global__ void __launch_bounds__(256, 2) attn_ca(
    const float* __restrict__ Q, const float* __restrict__ KV,
    float* __restrict__ po, float* __restrict__ pm, float* __restrict__ pl)
{
    extern __shared__ uint32_t sm[];
    const uint32_t smb = smem_u32(sm);

    const int qt = blockIdx.x, h = blockIdx.y;
    const int b = blockIdx.z >> 2, sp = blockIdx.z & 3;
    const int tid = threadIdx.x, w = tid >> 5, lane = tid & 31;
    const int g = lane >> 2, kq = lane & 3;

    // ---- stage Q tile (coalesced) into smem, then read A-fragments
    {
        const float* qsrc = Q + ((size_t)(b * NLAT + qt * 128)) * DI_ + h * DH_;
#pragma unroll
        for (int i = 0; i < 8; i++) {
            int idx = tid + i * 256;
            int r = idx >> 4, c4 = idx & 15;
            float4 v = *(const float4*)(qsrc + (size_t)r * DI_ + c4 * 4);
            *(float4*)(sm + r * 68 + c4 * 4) = v;
        }
    }
    __syncthreads();
    uint32_t qf[8][4];
    {
        const int r0 = w * 16 + g;
#pragma unroll
        for (int s = 0; s < 8; s++) {
            qf[s][0] = sm[r0 * 68 + 8 * s + kq];
            qf[s][1] = sm[(r0 + 8) * 68 + 8 * s + kq];
            qf[s][2] = sm[r0 * 68 + 8 * s + kq + 4];
            qf[s][3] = sm[(r0 + 8) * 68 + 8 * s + kq + 4];
        }
    }
    __syncthreads();

    float o[8][4];
#pragma unroll
    for (int dt = 0; dt < 8; dt++)
#pragma unroll
        for (int j = 0; j < 4; j++) o[dt][j] = 0.f;
    float mA = -INFINITY, mB = -INFINITY, lA = 0.f, lB = 0.f;

    const float* kvB = KV + (size_t)b * MTOT * KV_LD + h * DH_
                          + (size_t)(sp * SEGK) * KV_LD;

    auto issue = [&](int t) {
        const uint32_t base = smb + (t & 1) * STG_W * 4;
        const float* kp = kvB + (size_t)(t * 64) * KV_LD;
#pragma unroll
        for (int i = 0; i < 4; i++) {
            int idx = tid + i * 256;
            int r = idx >> 4, c = idx & 15;
            const float* src = kp + (size_t)r * KV_LD + c * 4;
            cpa16(base + (uint32_t)((r * KPAD + c * 4) << 2), src);
            cpa16(base + (uint32_t)((64 * KPAD + r * VPAD + c * 4) << 2), src + 512);
        }
    };

    issue(0); CPA_COMMIT();
    issue(1); CPA_COMMIT();

    for (int t = 0; t < NT_; ++t) {
        if (t == NT_ - 1) { CPA_WAIT(0); } else { CPA_WAIT(1); }
        __syncthreads();

        const uint32_t* sK = sm + (t & 1) * STG_W;
        const uint32_t* sV = sK + 64 * KPAD;

        // ---- S = Q K^T (log2 domain; scale pre-folded into Wq)
        float s[8][4];
#pragma unroll
        for (int nt = 0; nt < 8; nt++)
#pragma unroll
            for (int j = 0; j < 4; j++) s[nt][j] = 0.f;
#pragma unroll
        for (int ks = 0; ks < 8; ks++) {
#pragma unroll
            for (int nt = 0; nt < 8; nt++) {
                int i0 = (8 * nt + g) * KPAD + 8 * ks + kq;
                MMA_TF32(s[nt], qf[ks][0], qf[ks][1], qf[ks][2], qf[ks][3],
                         sK[i0], sK[i0 + 4]);
            }
        }

        // ---- online softmax (exp2)
        float tA = -INFINITY, tB = -INFINITY;
#pragma unroll
        for (int nt = 0; nt < 8; nt++) {
            tA = fmaxf(tA, fmaxf(s[nt][0], s[nt][1]));
            tB = fmaxf(tB, fmaxf(s[nt][2], s[nt][3]));
        }
        tA = fmaxf(tA, __shfl_xor_sync(0xffffffffu, tA, 1));
        tA = fmaxf(tA, __shfl_xor_sync(0xffffffffu, tA, 2));
        tB = fmaxf(tB, __shfl_xor_sync(0xffffffffu, tB, 1));
        tB = fmaxf(tB, __shfl_xor_sync(0xffffffffu, tB, 2));

        float mnA = fmaxf(mA, tA), mnB = fmaxf(mB, tB);
        float scA = exp2f(mA - mnA), scB = exp2f(mB - mnB);
        mA = mnA; mB = mnB;

        float suA = 0.f, suB = 0.f;
#pragma unroll
        for (int nt = 0; nt < 8; nt++) {
            s[nt][0] = exp2f(s[nt][0] - mnA); suA += s[nt][0];
            s[nt][1] = exp2f(s[nt][1] - mnA); suA += s[nt][1];
            s[nt][2] = exp2f(s[nt][2] - mnB); suB += s[nt][2];
            s[nt][3] = exp2f(s[nt][3] - mnB); suB += s[nt][3];
        }
        suA += __shfl_xor_sync(0xffffffffu, suA, 1);
        suA += __shfl_xor_sync(0xffffffffu, suA, 2);
        suB += __shfl_xor_sync(0xffffffffu, suB, 1);
        suB += __shfl_xor_sync(0xffffffffu, suB, 2);
        lA = lA * scA + suA;
        lB = lB * scB + suB;
#pragma unroll
        for (int dt = 0; dt < 8; dt++) {
            o[dt][0] *= scA; o[dt][1] *= scA;
            o[dt][2] *= scB; o[dt][3] *= scB;
        }

        // ---- O += P V  (P C-layout -> A-fragment via quad shuffles)
        const int src  = (lane & ~3) | (kq >> 1);
        const int src2 = src | 2;
        const int odd  = kq & 1;
#pragma unroll
        for (int ks = 0; ks < 8; ks++) {
            float f00 = __shfl_sync(0xffffffffu, s[ks][0], src);
            float f01 = __shfl_sync(0xffffffffu, s[ks][1], src);
            float f20 = __shfl_sync(0xffffffffu, s[ks][2], src);
            float f21 = __shfl_sync(0xffffffffu, s[ks][3], src);
            float h00 = __shfl_sync(0xffffffffu, s[ks][0], src2);
            float h01 = __shfl_sync(0xffffffffu, s[ks][1], src2);
            float h20 = __shfl_sync(0xffffffffu, s[ks][2], src2);
            float h21 = __shfl_sync(0xffffffffu, s[ks][3], src2);
            uint32_t a0 = __float_as_uint(odd ? f01 : f00);
            uint32_t a1 = __float_as_uint(odd ? f21 : f20);
            uint32_t a2 = __float_as_uint(odd ? h01 : h00);
            uint32_t a3 = __float_as_uint(odd ? h21 : h20);
            const int vr0 = (8 * ks + kq) * VPAD + g;
            const int vr1 = (8 * ks + kq + 4) * VPAD + g;
#pragma unroll
            for (int dt = 0; dt < 8; dt++) {
                MMA_TF32(o[dt], a0, a1, a2, a3,
                         sV[vr0 + 8 * dt], sV[vr1 + 8 * dt]);
            }
        }

        __syncthreads();                        // stage (t&1) free before reissue
        if (t + 2 < NT_) { issue(t + 2); CPA_COMMIT(); }
    }

    // ---- store unnormalized partials + (m, l)
    const int pidx = (((b * H_ + h) * 4 + qt) * SPLIT + sp);
    float* pob = po + (size_t)pidx * 128 * 64;
    const int r0 = w * 16 + g;
#pragma unroll
    for (int dt = 0; dt < 8; dt++) {
        *(float2*)&pob[r0 * 64 + 8 * dt + 2 * kq]       = make_float2(o[dt][0], o[dt][1]);
        *(float2*)&pob[(r0 + 8) * 64 + 8 * dt + 2 * kq] = make_float2(o[dt][2], o[dt][3]);
    }
    if (kq == 0) {
        pm[pidx * 128 + r0]     = mA; pm[pidx * 128 + r0 + 8] = mB;
        pl[pidx * 128 + r0]     = lA; pl[pidx * 128 + r0 + 8] = lB;
    }
}

// ===========================================================================
// Merge split-K partials -> O
// ===========================================================================
__global__ __launch_bounds__(256) void merge_k(
    const float* __restrict__ po, const float* __restrict__ pm,
    const float* __restrict__ pl, float* __restrict__ O)
{
    const int qt = blockIdx.x, h = blockIdx.y, b = blockIdx.z;
    const int tid = threadIdx.x;
    const int row = tid >> 1, colh = (tid & 1) * 32;
    const int base = ((b * H_ + h) * 4 + qt) * SPLIT;

    float m[SPLIT], l[SPLIT];
#pragma unroll
    for (int s = 0; s < SPLIT; s++) {
        m[s] = pm[(base + s) * 128 + row];
        l[s] = pl[(base + s) * 128 + row];
    }
    float M = fmaxf(fmaxf(m[0], m[1]), fmaxf(m[2], m[3]));
    float wgt[SPLIT], L = 0.f;
#pragma unroll
    for (int s = 0; s < SPLIT; s++) { wgt[s] = exp2f(m[s] - M); L += wgt[s] * l[s]; }
    const float inv = 1.f / L;
#pragma unroll
    for (int s = 0; s < SPLIT; s++) wgt[s] *= inv;

    float* op = O + ((size_t)(b * NLAT + qt * 128 + row)) * DI_ + h * DH_ + colh;
#pragma unroll
    for (int j = 0; j < 8; j++) {
        float4 acc = make_float4(0.f, 0.f, 0.f, 0.f);
#pragma unroll
        for (int s = 0; s < SPLIT; s++) {
            float4 v = *(const float4*)&po[((size_t)(base + s) * 128 + row) * 64 + colh + 4 * j];
            acc.x += wgt[s] * v.x; acc.y += wgt[s] * v.y;
            acc.z += wgt[s] * v.z; acc.w += wgt[s] * v.w;
        }
        *(float4*)(op + 4 * j) = acc;
    }
}

// ===========================================================================
// Out-proj: A-split tf32 mma — C = (A_hi + A_lo) * tf32(W), near-fp32 accuracy
// CTA 128x128, K-tile 32, single-buffered, register-prefetched LDG.
// ===========================================================================
#define OUT_SMEM (3 * 4096 * 4)   // Ah, Al, Bh (128x32 words each) = 48KB

__global__ void __launch_bounds__(256) out_proj(
    const float* __restrict__ A, const float* __restrict__ W,
    float* __restrict__ C)
{
    extern __shared__ uint32_t sm[];
    uint32_t* sAh = sm;
    uint32_t* sAl = sm + 4096;
    uint32_t* sBh = sm + 8192;

    const int tid = threadIdx.x, w = tid >> 5, lane = tid & 31;
    const int g = lane >> 2, kq = lane & 3;
    const int b = blockIdx.z;
    const int rowBase = blockIdx.y * 128, colBase = blockIdx.x * 128;
    const int wm = (w >> 2) * 64, wn = (w & 3) * 32;

    const float* Ab = A + (size_t)b * NLAT * DI_;
    float*       Cb = C + (size_t)b * NLAT * DIM_;

    float c[4][4][4];
#pragma unroll
    for (int mt = 0; mt < 4; mt++)
#pragma unroll
        for (int nt = 0; nt < 4; nt++)
#pragma unroll
            for (int j = 0; j < 4; j++) c[mt][nt][j] = 0.f;

    const int sr = tid >> 1, sc0 = (tid & 1) * 16;
    const float* srcA = Ab + (size_t)(rowBase + sr) * DI_;
    const float* srcW = W + (size_t)(colBase + sr) * DI_;

    float4 ar[4], br[4];
    auto ldg = [&](int k0) {
#pragma unroll
        for (int i = 0; i < 4; i++) {
            ar[i] = *(const float4*)(srcA + k0 + sc0 + 4 * i);
            br[i] = *(const float4*)(srcW + k0 + sc0 + 4 * i);
        }
    };
    ldg(0);

    const int sw = (sr & 7) << 2;
    const int KT = DI_ >> 5;   // 16
    for (int kt = 0; kt < KT; ++kt) {
        __syncthreads();
#pragma unroll
        for (int i = 0; i < 4; i++) {
            int idx = sr * 32 + ((sc0 + 4 * i) ^ sw);
            uint32_t hx = f2t(ar[i].x), hy = f2t(ar[i].y),
                     hz = f2t(ar[i].z), hw = f2t(ar[i].w);
            *(uint4*)&sAh[idx] = make_uint4(hx, hy, hz, hw);
            *(uint4*)&sAl[idx] = make_uint4(
                f2t(ar[i].x - __uint_as_float(hx)), f2t(ar[i].y - __uint_as_float(hy)),
                f2t(ar[i].z - __uint_as_float(hz)), f2t(ar[i].w - __uint_as_float(hw)));
            *(uint4*)&sBh[idx] = make_uint4(f2t(br[i].x), f2t(br[i].y),
                                            f2t(br[i].z), f2t(br[i].w));
        }
        __syncthreads();
        if (kt + 1 < KT) ldg((kt + 1) * 32);

#pragma unroll
        for (int ks = 0; ks < 4; ++ks) {
            uint32_t ah[4][4], al[4][4], bf[4][2];
            const int colw = (ks * 8 + kq) ^ (g << 2);
#pragma unroll
            for (int mt = 0; mt < 4; mt++) {
                int r0 = wm + mt * 16 + g;
                int i0 = r0 * 32 + colw, i1 = (r0 + 8) * 32 + colw;
                ah[mt][0] = sAh[i0];     ah[mt][1] = sAh[i1];
                ah[mt][2] = sAh[i0 ^ 4]; ah[mt][3] = sAh[i1 ^ 4];
                al[mt][0] = sAl[i0];     al[mt][1] = sAl[i1];
                al[mt][2] = sAl[i0 ^ 4]; al[mt][3] = sAl[i1 ^ 4];
            }
#pragma unroll
            for (int nt = 0; nt < 4; nt++) {
                int i0 = (wn + nt * 8 + g) * 32 + colw;
                bf[nt][0] = sBh[i0]; bf[nt][1] = sBh[i0 ^ 4];
            }
#pragma unroll
            for (int mt = 0; mt < 4; mt++)
#pragma unroll
                for (int nt = 0; nt < 4; nt++) {
                    MMA_TF32(c[mt][nt], ah[mt][0], ah[mt][1], ah[mt][2], ah[mt][3],
                             bf[nt][0], bf[nt][1]);
                    MMA_TF32(c[mt][nt], al[mt][0], al[mt][1], al[mt][2], al[mt][3],
                             bf[nt][0], bf[nt][1]);
                }
        }
    }

#pragma unroll
    for (int mt = 0; mt < 4; mt++) {
        int row0 = rowBase + wm + mt * 16 + g;
#pragma unroll
        for (int nt = 0; nt < 4; nt++) {
            int col = colBase + wn + nt * 8 + 2 * kq;
            *(float2*)&Cb[(size_t)row0 * DIM_ + col] =
                make_float2(c[mt][nt][0], c[mt][nt][1]);
            *(float2*)&Cb[(size_t)(row0 + 8) * DIM_ + col] =
                make_float2(c[mt][nt][2], c[mt][nt][3]);
        }
    }
}

// ===========================================================================
// Launch
// ===========================================================================
extern "C" void kernel_launch(void* const* d_in, const int* in_sizes, int n_in,
                              void* d_out, int out_size)
{
    const float* x    = (const float*)d_in[0];
    const float* ctx  = (const float*)d_in[1];
    const float* Wq   = (const float*)d_in[2];
    const float* Wkv  = (const float*)d_in[3];
    const float* Wout = (const float*)d_in[4];
    float* out = (float*)d_out;

    float *pXT, *pCT, *pWQ, *pWKV, *pQ, *pKV, *pO, *pPO, *pPM, *pPL;
    cudaGetSymbolAddress((void**)&pXT,  g_xt);
    cudaGetSymbolAddress((void**)&pCT,  g_ctxt);
    cudaGetSymbolAddress((void**)&pWQ,  g_wqt);
    cudaGetSymbolAddress((void**)&pWKV, g_wkvt);
    cudaGetSymbolAddress((void**)&pQ,   g_Q);
    cudaGetSymbolAddress((void**)&pKV,  g_KV);
    cudaGetSymbolAddress((void**)&pO,   g_O);
    cudaGetSymbolAddress((void**)&pPO,  g_PO);
    cudaGetSymbolAddress((void**)&pPM,  g_PM);
    cudaGetSymbolAddress((void**)&pPL,  g_PL);

    cudaFuncSetAttribute(gemm_ca,  cudaFuncAttributeMaxDynamicSharedMemorySize, GEMM_SMEM);
    cudaFuncSetAttribute(attn_ca,  cudaFuncAttributeMaxDynamicSharedMemorySize, ATT_SMEM);
    cudaFuncSetAttribute(out_proj, cudaFuncAttributeMaxDynamicSharedMemorySize, OUT_SMEM);

    // 0. round inputs to tf32 (+ fold 0.125*log2e into Wq)
    {
        size_t total4 = ((size_t)B_ * NLAT * DIM_ + (size_t)B_ * NCTX * DIM_
                         + (size_t)DI_ * DIM_ + (size_t)2 * DI_ * DIM_) / 4;
        prep_round<<<(unsigned)((total4 + 255) / 256), 256>>>(
            x, ctx, Wq, Wkv, pXT, pCT, pWQ, pWKV);
    }

    // 1. Q = x @ (Wq*scale)^T   (rounded output)
    gemm_ca<<<dim3(DI_ / 128, NLAT / 128, B_), 256, GEMM_SMEM>>>(
        pXT, (size_t)NLAT * DIM_, NLAT, pXT, 0, pWQ,
        pQ, (size_t)NLAT * DI_, DI_, DIM_, 1);

    // 2. KV = concat(x, ctx) @ Wkv^T   (rounded output)
    gemm_ca<<<dim3(KV_LD / 128, MTOT / 128, B_), 256, GEMM_SMEM>>>(
        pXT, (size_t)NLAT * DIM_, NLAT, pCT, (size_t)NCTX * DIM_, pWKV,
        pKV, (size_t)MTOT * KV_LD, KV_LD, DIM_, 1);

    // 3. attention partials (split-K by 4)
    attn_ca<<<dim3(NLAT / 128, H_, B_ * SPLIT), 256, ATT_SMEM>>>(
        pQ, pKV, pPO, pPM, pPL);

    // 4. merge partials -> O
    merge_k<<<dim3(NLAT / 128, H_, B_), 256>>>(pPO, pPM, pPL, pO);

    // 5. out = O @ Wout^T   (A-split tf32, near-fp32)
    out_proj<<<dim3(DIM_ / 128, NLAT / 128, B_), 256, OUT_SMEM>>>(pO, Wout, out);
}

// round 5
// speedup vs baseline: 5.8693x; 1.0686x over previous
#include <cuda_runtime.h>
#include <math.h>
#include <cstdint>

// Problem constants
#define B_    4
#define NLAT  512
#define NCTX  4096
#define MTOT  4608
#define DIM_  512
#define H_    8
#define DH_   64
#define DI_   512
#define KV_LD 1024            // K (512) | V (512) per row
#define SPLIT 4
#define SEGK  (MTOT / SPLIT)  // 1152 keys per split
#define NT_   (SEGK / 64)     // 18 tiles per split

// Scratch (allocation-free per harness rules)
__device__ float g_xt  [(size_t)B_ * NLAT * DIM_];
__device__ float g_ctxt[(size_t)B_ * NCTX * DIM_];
__device__ float g_wqt [(size_t)DI_ * DIM_];
__device__ float g_wkvt[(size_t)2 * DI_ * DIM_];
__device__ float g_Q   [(size_t)B_ * NLAT * DI_];
__device__ float g_KV  [(size_t)B_ * MTOT * KV_LD];
__device__ float g_O   [(size_t)B_ * NLAT * DI_];
__device__ float g_PO  [(size_t)B_ * H_ * 4 * SPLIT * 128 * 64];
__device__ float g_PM  [(size_t)B_ * H_ * 4 * SPLIT * 128];
__device__ float g_PL  [(size_t)B_ * H_ * 4 * SPLIT * 128];

// ---------------------------------------------------------------------------
// Helpers
// ---------------------------------------------------------------------------
__device__ __forceinline__ uint32_t f2t(float f) {
    uint32_t r;
    asm("cvt.rna.tf32.f32 %0, %1;" : "=r"(r) : "f"(f));
    return r;
}
__device__ __forceinline__ uint32_t smem_u32(const void* p) {
    uint32_t a;
    asm("{ .reg .u64 t; cvta.to.shared.u64 t, %1; cvt.u32.u64 %0, t; }"
        : "=r"(a) : "l"(p));
    return a;
}
__device__ __forceinline__ void cpa16(uint32_t dst, const void* src) {
    asm volatile("cp.async.cg.shared.global [%0], [%1], 16;" :: "r"(dst), "l"(src));
}
#define CPA_COMMIT() asm volatile("cp.async.commit_group;" ::: "memory")
#define CPA_WAIT(n)  asm volatile("cp.async.wait_group %0;" :: "n"(n) : "memory")

#define MMA_TF32(C, A0, A1, A2, A3, B0, B1) \
    asm volatile("mma.sync.aligned.m16n8k8.row.col.f32.tf32.tf32.f32 " \
        "{%0,%1,%2,%3}, {%4,%5,%6,%7}, {%8,%9}, {%0,%1,%2,%3};" \
        : "+f"((C)[0]), "+f"((C)[1]), "+f"((C)[2]), "+f"((C)[3]) \
        : "r"(A0), "r"(A1), "r"(A2), "r"(A3), "r"(B0), "r"(B1))

// ===========================================================================
// Prep: round inputs to tf32 once (Wq also folded with 0.125 * log2(e)).
// ===========================================================================
__global__ __launch_bounds__(256) void prep_round(
    const float* __restrict__ x, const float* __restrict__ ctx,
    const float* __restrict__ Wq, const float* __restrict__ Wkv,
    float* __restrict__ xt, float* __restrict__ ctxt,
    float* __restrict__ wqt, float* __restrict__ wkvt)
{
    const size_t nx = (size_t)B_ * NLAT * DIM_ / 4;
    const size_t nc = (size_t)B_ * NCTX * DIM_ / 4;
    const size_t nq = (size_t)DI_ * DIM_ / 4;
    const size_t nk = (size_t)2 * DI_ * DIM_ / 4;
    size_t i = (size_t)blockIdx.x * 256 + threadIdx.x;

    const float* src; float* dst; float s = 1.f;
    if (i < nx)                { src = x;   dst = xt; }
    else if ((i -= nx) < nc)   { src = ctx; dst = ctxt; }
    else if ((i -= nc) < nq)   { src = Wq;  dst = wqt; s = 0.18033688011112042f; }
    else if ((i -= nq) < nk)   { src = Wkv; dst = wkvt; }
    else return;

    float4 v = *(const float4*)(src + 4 * i);
    float4 o;
    o.x = __uint_as_float(f2t(v.x * s));
    o.y = __uint_as_float(f2t(v.y * s));
    o.z = __uint_as_float(f2t(v.z * s));
    o.w = __uint_as_float(f2t(v.w * s));
    *(float4*)(dst + 4 * i) = o;
}

// ===========================================================================
// cp.async tf32 GEMM (NT): C[b,r,c] = sum_k A[b,r,k] * W[c,k]
// CTA 128x128, 8 warps (64x32 each), K-tile 32, 3-stage cp.async pipeline.
// k-permutation: mma-k kq <-> col 2kq, kq+4 <-> 2kq+1 -> all fragment pairs
// are adjacent words -> LDS.64. Swizzle: col ^ ((row&3)<<3) (conflict-free at
// 8B granularity for both fragment reads and 16B cp.async stores).
// ===========================================================================
#define GEMM_SMEM (3 * 8192 * 4)   // 3 stages x (A 4096 + B 4096 words) = 96KB

__global__ void __launch_bounds__(256, 2) gemm_ca(
    const float* __restrict__ A1, size_t a1bs, int n1,
    const float* __restrict__ A2, size_t a2bs,
    const float* __restrict__ W,
    float* __restrict__ C, size_t cbs, int ldc, int K, int roundOut)
{
    extern __shared__ uint32_t sm[];
    const uint32_t smb = smem_u32(sm);

    const int tid = threadIdx.x, w = tid >> 5, lane = tid & 31;
    const int g = lane >> 2, kq = lane & 3;
    const int b = blockIdx.z;
    const int rowBase = blockIdx.y * 128, colBase = blockIdx.x * 128;
    const int wm = (w >> 2) * 64, wn = (w & 3) * 32;

    const float* A1b = A1 + (size_t)b * a1bs;
    const float* A2b = A2 + (size_t)b * a2bs;
    float*       Cb  = C  + (size_t)b * cbs;

    float c[4][4][4];
#pragma unroll
    for (int mt = 0; mt < 4; mt++)
#pragma unroll
        for (int nt = 0; nt < 4; nt++)
#pragma unroll
            for (int j = 0; j < 4; j++) c[mt][nt][j] = 0.f;

    auto issue = [&](int kt, int stage) {
        const int k0 = kt * 32;
        const uint32_t base = smb + stage * 8192 * 4;
#pragma unroll
        for (int i = 0; i < 4; i++) {
            int idx = tid + i * 256;        // 0..1023
            int r = idx >> 3, ch = idx & 7; // row, 16B chunk (4 words)
            int grow = rowBase + r;
            const float* srcA = ((grow < n1) ? (A1b + (size_t)grow * K)
                                             : (A2b + (size_t)(grow - n1) * K)) + k0 + ch * 4;
            uint32_t dA = base + (uint32_t)((r * 32 + ((ch * 4) ^ ((r & 3) << 3))) << 2);
            cpa16(dA, srcA);
            const float* srcB = W + (size_t)(colBase + r) * K + k0 + ch * 4;
            cpa16(dA + 4096 * 4, srcB);
        }
    };

    issue(0, 0); CPA_COMMIT();
    issue(1, 1); CPA_COMMIT();

    const int KT = K >> 5;   // 16
    for (int kt = 0; kt < KT; ++kt) {
        if (kt == KT - 1) { CPA_WAIT(0); } else { CPA_WAIT(1); }
        __syncthreads();
        if (kt + 2 < KT) { issue(kt + 2, (kt + 2) % 3); CPA_COMMIT(); }

        const uint32_t* sA = sm + (kt % 3) * 8192;
        const uint32_t* sB = sA + 4096;
#pragma unroll
        for (int ks = 0; ks < 4; ++ks) {
            uint32_t a[4][4], bf[4][2];
            const int colw = (8 * ks + 2 * kq) ^ ((g & 3) << 3);
#pragma unroll
            for (int mt = 0; mt < 4; mt++) {
                int r0 = wm + mt * 16 + g;
                uint2 ua = *(const uint2*)&sA[r0 * 32 + colw];
                uint2 ub = *(const uint2*)&sA[(r0 + 8) * 32 + colw];
                a[mt][0] = ua.x; a[mt][1] = ub.x;
                a[mt][2] = ua.y; a[mt][3] = ub.y;
            }
#pragma unroll
            for (int nt = 0; nt < 4; nt++) {
                uint2 vb = *(const uint2*)&sB[(wn + nt * 8 + g) * 32 + colw];
                bf[nt][0] = vb.x; bf[nt][1] = vb.y;
            }
#pragma unroll
            for (int mt = 0; mt < 4; mt++)
#pragma unroll
                for (int nt = 0; nt < 4; nt++)
                    MMA_TF32(c[mt][nt], a[mt][0], a[mt][1], a[mt][2], a[mt][3],
                             bf[nt][0], bf[nt][1]);
        }
    }

#pragma unroll
    for (int mt = 0; mt < 4; mt++) {
        int row0 = rowBase + wm + mt * 16 + g;
#pragma unroll
        for (int nt = 0; nt < 4; nt++) {
            int col = colBase + wn + nt * 8 + 2 * kq;
            float v0 = c[mt][nt][0], v1 = c[mt][nt][1];
            float v2 = c[mt][nt][2], v3 = c[mt][nt][3];
            if (roundOut) {
                v0 = __uint_as_float(f2t(v0)); v1 = __uint_as_float(f2t(v1));
                v2 = __uint_as_float(f2t(v2)); v3 = __uint_as_float(f2t(v3));
            }
            *(float2*)&Cb[(size_t)row0 * ldc + col]       = make_float2(v0, v1);
            *(float2*)&Cb[(size_t)(row0 + 8) * ldc + col] = make_float2(v2, v3);
        }
    }
}

// ===========================================================================
// Flash attention, split-K by 4, 3-stage cp.async, tf32 mma, 1 barrier/tile.
// k-permutation (kq <-> 2kq, kq+4 <-> 2kq+1) everywhere:
//  * QK: K b-frag pairs adjacent (LDS.64); Q a-frag cols permuted to match.
//  * PV: the QK C-fragment IS the PV A-fragment (s0,s2,s1,s3) - no shuffles.
//    V b-frag rows become 2kq / 2kq+1 (VPAD=68 keeps both conflict-free).
// Q staged into the stage-2 region before it is first needed for tiles.
// ===========================================================================
#define KPAD 72
#define VPAD 68
#define STG_W (64 * KPAD + 64 * VPAD)      // 8960 words per stage
#define ATT_SMEM (3 * STG_W * 4)           // 107520 B

__global__ void __launch_bounds__(256, 2) attn_ca(
    const float* __restrict__ Q, const float* __restrict__ KV,
    float* __restrict__ po, float* __restrict__ pm, float* __restrict__ pl)
{
    extern __shared__ uint32_t sm[];
    const uint32_t smb = smem_u32(sm);

    const int qt = blockIdx.x, h = blockIdx.y;
    const int b = blockIdx.z >> 2, sp = blockIdx.z & 3;
    const int tid = threadIdx.x, w = tid >> 5, lane = tid & 31;
    const int g = lane >> 2, kq = lane & 3;

    const float* kvB = KV + (size_t)b * MTOT * KV_LD + h * DH_
                          + (size_t)(sp * SEGK) * KV_LD;

    auto issue = [&](int t) {
        const uint32_t base = smb + (uint32_t)((t % 3) * STG_W * 4);
        const float* kp = kvB + (size_t)(t * 64) * KV_LD;
#pragma unroll
        for (int i = 0; i < 4; i++) {
            int idx = tid + i * 256;
            int r = idx >> 4, c = idx & 15;
            const float* src = kp + (size_t)r * KV_LD + c * 4;
            cpa16(base + (uint32_t)((r * KPAD + c * 4) << 2), src);
            cpa16(base + (uint32_t)((64 * KPAD + r * VPAD + c * 4) << 2), src + 512);
        }
    };

    issue(0); CPA_COMMIT();
    issue(1); CPA_COMMIT();

    // ---- stage Q tile into stage-2 region (overlapped with cp.async above)
    uint32_t* qs = sm + 2 * STG_W;
    {
        const float* qsrc = Q + ((size_t)(b * NLAT + qt * 128)) * DI_ + h * DH_;
#pragma unroll
        for (int i = 0; i < 8; i++) {
            int idx = tid + i * 256;
            int r = idx >> 4, c4 = idx & 15;
            float4 v = *(const float4*)(qsrc + (size_t)r * DI_ + c4 * 4);
            *(float4*)(qs + r * 68 + c4 * 4) = v;
        }
    }
    __syncthreads();

    // ---- Q A-fragments, columns permuted (2kq, 2kq+1) to match K pairs
    uint32_t qf[8][4];
    {
        const int r0 = w * 16 + g;
#pragma unroll
        for (int s = 0; s < 8; s++) {
            uint2 u0 = *(const uint2*)&qs[r0 * 68 + 8 * s + 2 * kq];
            uint2 u1 = *(const uint2*)&qs[(r0 + 8) * 68 + 8 * s + 2 * kq];
            qf[s][0] = u0.x; qf[s][1] = u1.x;
            qf[s][2] = u0.y; qf[s][3] = u1.y;
        }
    }

    float o[8][4];
#pragma unroll
    for (int dt = 0; dt < 8; dt++)
#pragma unroll
        for (int j = 0; j < 4; j++) o[dt][j] = 0.f;
    float mA = -INFINITY, mB = -INFINITY, lA = 0.f, lB = 0.f;

    for (int t = 0; t < NT_; ++t) {
        if (t == NT_ - 1) { CPA_WAIT(0); } else { CPA_WAIT(1); }
        __syncthreads();   // stage t ready; all warps done with stage (t-1)%3
        if (t + 2 < NT_) { issue(t + 2); CPA_COMMIT(); }

        const uint32_t* sK = sm + (t % 3) * STG_W;
        const uint32_t* sV = sK + 64 * KPAD;

        // ---- S = Q K^T (log2 domain; scale pre-folded into Wq)
        float s[8][4];
#pragma unroll
        for (int nt = 0; nt < 8; nt++)
#pragma unroll
            for (int j = 0; j < 4; j++) s[nt][j] = 0.f;
#pragma unroll
        for (int ks = 0; ks < 8; ks++) {
            const int dcol = 8 * ks + 2 * kq;
#pragma unroll
            for (int nt = 0; nt < 8; nt++) {
                uint2 kb = *(const uint2*)&sK[(8 * nt + g) * KPAD + dcol];
                MMA_TF32(s[nt], qf[ks][0], qf[ks][1], qf[ks][2], qf[ks][3],
                         kb.x, kb.y);
            }
        }

        // ---- online softmax (exp2)
        float tA = -INFINITY, tB = -INFINITY;
#pragma unroll
        for (int nt = 0; nt < 8; nt++) {
            tA = fmaxf(tA, fmaxf(s[nt][0], s[nt][1]));
            tB = fmaxf(tB, fmaxf(s[nt][2], s[nt][3]));
        }
        tA = fmaxf(tA, __shfl_xor_sync(0xffffffffu, tA, 1));
        tA = fmaxf(tA, __shfl_xor_sync(0xffffffffu, tA, 2));
        tB = fmaxf(tB, __shfl_xor_sync(0xffffffffu, tB, 1));
        tB = fmaxf(tB, __shfl_xor_sync(0xffffffffu, tB, 2));

        float mnA = fmaxf(mA, tA), mnB = fmaxf(mB, tB);
        float scA = exp2f(mA - mnA), scB = exp2f(mB - mnB);
        mA = mnA; mB = mnB;

        float suA = 0.f, suB = 0.f;
#pragma unroll
        for (int nt = 0; nt < 8; nt++) {
            s[nt][0] = exp2f(s[nt][0] - mnA); suA += s[nt][0];
            s[nt][1] = exp2f(s[nt][1] - mnA); suA += s[nt][1];
            s[nt][2] = exp2f(s[nt][2] - mnB); suB += s[nt][2];
            s[nt][3] = exp2f(s[nt][3] - mnB); suB += s[nt][3];
        }
        suA += __shfl_xor_sync(0xffffffffu, suA, 1);
        suA += __shfl_xor_sync(0xffffffffu, suA, 2);
        suB += __shfl_xor_sync(0xffffffffu, suB, 1);
        suB += __shfl_xor_sync(0xffffffffu, suB, 2);
        lA = lA * scA + suA;
        lB = lB * scB + suB;

        if (__any_sync(0xffffffffu, (scA != 1.f) || (scB != 1.f))) {
#pragma unroll
            for (int dt = 0; dt < 8; dt++) {
                o[dt][0] *= scA; o[dt][1] *= scA;
                o[dt][2] *= scB; o[dt][3] *= scB;
            }
        }

        // ---- O += P V : C-fragment reused directly as A-fragment
#pragma unroll
        for (int ks = 0; ks < 8; ks++) {
            uint32_t a0 = __float_as_uint(s[ks][0]);
            uint32_t a1 = __float_as_uint(s[ks][2]);
            uint32_t a2 = __float_as_uint(s[ks][1]);
            uint32_t a3 = __float_as_uint(s[ks][3]);
            const int vr0 = (8 * ks + 2 * kq) * VPAD + g;
            const int vr1 = vr0 + VPAD;
#pragma unroll
            for (int dt = 0; dt < 8; dt++) {
                MMA_TF32(o[dt], a0, a1, a2, a3,
                         sV[vr0 + 8 * dt], sV[vr1 + 8 * dt]);
            }
        }
    }

    // ---- store unnormalized partials + (m, l)
    const int pidx = (((b * H_ + h) * 4 + qt) * SPLIT + sp);
    float* pob = po + (size_t)pidx * 128 * 64;
    const int r0 = w * 16 + g;
#pragma unroll
    for (int dt = 0; dt < 8; dt++) {
        *(float2*)&pob[r0 * 64 + 8 * dt + 2 * kq]       = make_float2(o[dt][0], o[dt][1]);
        *(float2*)&pob[(r0 + 8) * 64 + 8 * dt + 2 * kq] = make_float2(o[dt][2], o[dt][3]);
    }
    if (kq == 0) {
        pm[pidx * 128 + r0]     = mA; pm[pidx * 128 + r0 + 8] = mB;
        pl[pidx * 128 + r0]     = lA; pl[pidx * 128 + r0 + 8] = lB;
    }
}

// ===========================================================================
// Merge split-K partials -> O
// ===========================================================================
__global__ __launch_bounds__(256) void merge_k(
    const float* __restrict__ po, const float* __restrict__ pm,
    const float* __restrict__ pl, float* __restrict__ O)
{
    const int qt = blockIdx.x, h = blockIdx.y, b = blockIdx.z;
    const int tid = threadIdx.x;
    const int row = tid >> 1, colh = (tid & 1) * 32;
    const int base = ((b * H_ + h) * 4 + qt) * SPLIT;

    float m[SPLIT], l[SPLIT];
#pragma unroll
    for (int s = 0; s < SPLIT; s++) {
        m[s] = pm[(base + s) * 128 + row];
        l[s] = pl[(base + s) * 128 + row];
    }
    float M = fmaxf(fmaxf(m[0], m[1]), fmaxf(m[2], m[3]));
    float wgt[SPLIT], L = 0.f;
#pragma unroll
    for (int s = 0; s < SPLIT; s++) { wgt[s] = exp2f(m[s] - M); L += wgt[s] * l[s]; }
    const float inv = 1.f / L;
#pragma unroll
    for (int s = 0; s < SPLIT; s++) wgt[s] *= inv;

    float* op = O + ((size_t)(b * NLAT + qt * 128 + row)) * DI_ + h * DH_ + colh;
#pragma unroll
    for (int j = 0; j < 8; j++) {
        float4 acc = make_float4(0.f, 0.f, 0.f, 0.f);
#pragma unroll
        for (int s = 0; s < SPLIT; s++) {
            float4 v = *(const float4*)&po[((size_t)(base + s) * 128 + row) * 64 + colh + 4 * j];
            acc.x += wgt[s] * v.x; acc.y += wgt[s] * v.y;
            acc.z += wgt[s] * v.z; acc.w += wgt[s] * v.w;
        }
        *(float4*)(op + 4 * j) = acc;
    }
}

// ===========================================================================
// Out-proj: A-split tf32 mma - C = (A_hi + A_lo) * tf32(W), near-fp32
// ===========================================================================
#define OUT_SMEM (3 * 4096 * 4)   // Ah, Al, Bh (128x32 words each) = 48KB

__global__ void __launch_bounds__(256) out_proj(
    const float* __restrict__ A, const float* __restrict__ W,
    float* __restrict__ C)
{
    extern __shared__ uint32_t sm[];
    uint32_t* sAh = sm;
    uint32_t* sAl = sm + 4096;
    uint32_t* sBh = sm + 8192;

    const int tid = threadIdx.x, w = tid >> 5, lane = tid & 31;
    const int g = lane >> 2, kq = lane & 3;
    const int b = blockIdx.z;
    const int rowBase = blockIdx.y * 128, colBase = blockIdx.x * 128;
    const int wm = (w >> 2) * 64, wn = (w & 3) * 32;

    const float* Ab = A + (size_t)b * NLAT * DI_;
    float*       Cb = C + (size_t)b * NLAT * DIM_;

    float c[4][4][4];
#pragma unroll
    for (int mt = 0; mt < 4; mt++)
#pragma unroll
        for (int nt = 0; nt < 4; nt++)
#pragma unroll
            for (int j = 0; j < 4; j++) c[mt][nt][j] = 0.f;

    const int sr = tid >> 1, sc0 = (tid & 1) * 16;
    const float* srcA = Ab + (size_t)(rowBase + sr) * DI_;
    const float* srcW = W + (size_t)(colBase + sr) * DI_;

    float4 ar[4], br[4];
    auto ldg = [&](int k0) {
#pragma unroll
        for (int i = 0; i < 4; i++) {
            ar[i] = *(const float4*)(srcA + k0 + sc0 + 4 * i);
            br[i] = *(const float4*)(srcW + k0 + sc0 + 4 * i);
        }
    };
    ldg(0);

    const int sw = (sr & 7) << 2;
    const int KT = DI_ >> 5;   // 16
    for (int kt = 0; kt < KT; ++kt) {
        __syncthreads();
#pragma unroll
        for (int i = 0; i < 4; i++) {
            int idx = sr * 32 + ((sc0 + 4 * i) ^ sw);
            uint32_t hx = f2t(ar[i].x), hy = f2t(ar[i].y),
                     hz = f2t(ar[i].z), hw = f2t(ar[i].w);
            *(uint4*)&sAh[idx] = make_uint4(hx, hy, hz, hw);
            *(uint4*)&sAl[idx] = make_uint4(
                f2t(ar[i].x - __uint_as_float(hx)), f2t(ar[i].y - __uint_as_float(hy)),
                f2t(ar[i].z - __uint_as_float(hz)), f2t(ar[i].w - __uint_as_float(hw)));
            *(uint4*)&sBh[idx] = make_uint4(f2t(br[i].x), f2t(br[i].y),
                                            f2t(br[i].z), f2t(br[i].w));
        }
        __syncthreads();
        if (kt + 1 < KT) ldg((kt + 1) * 32);

#pragma unroll
        for (int ks = 0; ks < 4; ++ks) {
            uint32_t ah[4][4], al[4][4], bf[4][2];
            const int colw = (ks * 8 + kq) ^ (g << 2);
#pragma unroll
            for (int mt = 0; mt < 4; mt++) {
                int r0 = wm + mt * 16 + g;
                int i0 = r0 * 32 + colw, i1 = (r0 + 8) * 32 + colw;
                ah[mt][0] = sAh[i0];     ah[mt][1] = sAh[i1];
                ah[mt][2] = sAh[i0 ^ 4]; ah[mt][3] = sAh[i1 ^ 4];
                al[mt][0] = sAl[i0];     al[mt][1] = sAl[i1];
                al[mt][2] = sAl[i0 ^ 4]; al[mt][3] = sAl[i1 ^ 4];
            }
#pragma unroll
            for (int nt = 0; nt < 4; nt++) {
                int i0 = (wn + nt * 8 + g) * 32 + colw;
                bf[nt][0] = sBh[i0]; bf[nt][1] = sBh[i0 ^ 4];
            }
#pragma unroll
            for (int mt = 0; mt < 4; mt++)
#pragma unroll
                for (int nt = 0; nt < 4; nt++) {
                    MMA_TF32(c[mt][nt], ah[mt][0], ah[mt][1], ah[mt][2], ah[mt][3],
                             bf[nt][0], bf[nt][1]);
                    MMA_TF32(c[mt][nt], al[mt][0], al[mt][1], al[mt][2], al[mt][3],
                             bf[nt][0], bf[nt][1]);
                }
        }
    }

#pragma unroll
    for (int mt = 0; mt < 4; mt++) {
        int row0 = rowBase + wm + mt * 16 + g;
#pragma unroll
        for (int nt = 0; nt < 4; nt++) {
            int col = colBase + wn + nt * 8 + 2 * kq;
            *(float2*)&Cb[(size_t)row0 * DIM_ + col] =
                make_float2(c[mt][nt][0], c[mt][nt][1]);
            *(float2*)&Cb[(size_t)(row0 + 8) * DIM_ + col] =
                make_float2(c[mt][nt][2], c[mt][nt][3]);
        }
    }
}

// ===========================================================================
// Launch
// ===========================================================================
extern "C" void kernel_launch(void* const* d_in, const int* in_sizes, int n_in,
                              void* d_out, int out_size)
{
    const float* x    = (const float*)d_in[0];
    const float* ctx  = (const float*)d_in[1];
    const float* Wq   = (const float*)d_in[2];
    const float* Wkv  = (const float*)d_in[3];
    const float* Wout = (const float*)d_in[4];
    float* out = (float*)d_out;

    float *pXT, *pCT, *pWQ, *pWKV, *pQ, *pKV, *pO, *pPO, *pPM, *pPL;
    cudaGetSymbolAddress((void**)&pXT,  g_xt);
    cudaGetSymbolAddress((void**)&pCT,  g_ctxt);
    cudaGetSymbolAddress((void**)&pWQ,  g_wqt);
    cudaGetSymbolAddress((void**)&pWKV, g_wkvt);
    cudaGetSymbolAddress((void**)&pQ,   g_Q);
    cudaGetSymbolAddress((void**)&pKV,  g_KV);
    cudaGetSymbolAddress((void**)&pO,   g_O);
    cudaGetSymbolAddress((void**)&pPO,  g_PO);
    cudaGetSymbolAddress((void**)&pPM,  g_PM);
    cudaGetSymbolAddress((void**)&pPL,  g_PL);

    cudaFuncSetAttribute(gemm_ca,  cudaFuncAttributeMaxDynamicSharedMemorySize, GEMM_SMEM);
    cudaFuncSetAttribute(attn_ca,  cudaFuncAttributeMaxDynamicSharedMemorySize, ATT_SMEM);
    cudaFuncSetAttribute(out_proj, cudaFuncAttributeMaxDynamicSharedMemorySize, OUT_SMEM);

    // 0. round inputs to tf32 (+ fold 0.125*log2e into Wq)
    {
        size_t total4 = ((size_t)B_ * NLAT * DIM_ + (size_t)B_ * NCTX * DIM_
                         + (size_t)DI_ * DIM_ + (size_t)2 * DI_ * DIM_) / 4;
        prep_round<<<(unsigned)((total4 + 255) / 256), 256>>>(
            x, ctx, Wq, Wkv, pXT, pCT, pWQ, pWKV);
    }

    // 1. Q = x @ (Wq*scale)^T   (rounded output)
    gemm_ca<<<dim3(DI_ / 128, NLAT / 128, B_), 256, GEMM_SMEM>>>(
        pXT, (size_t)NLAT * DIM_, NLAT, pXT, 0, pWQ,
        pQ, (size_t)NLAT * DI_, DI_, DIM_, 1);

    // 2. KV = concat(x, ctx) @ Wkv^T   (rounded output)
    gemm_ca<<<dim3(KV_LD / 128, MTOT / 128, B_), 256, GEMM_SMEM>>>(
        pXT, (size_t)NLAT * DIM_, NLAT, pCT, (size_t)NCTX * DIM_, pWKV,
        pKV, (size_t)MTOT * KV_LD, KV_LD, DIM_, 1);

    // 3. attention partials (split-K by 4)
    attn_ca<<<dim3(NLAT / 128, H_, B_ * SPLIT), 256, ATT_SMEM>>>(
        pQ, pKV, pPO, pPM, pPL);

    // 4. merge partials -> O
    merge_k<<<dim3(NLAT / 128, H_, B_), 256>>>(pPO, pPM, pPL, pO);

    // 5. out = O @ Wout^T   (A-split tf32, near-fp32)
    out_proj<<<dim3(DIM_ / 128, NLAT / 128, B_), 256, OUT_SMEM>>>(pO, Wout, out);
}

// round 6
// speedup vs baseline: 6.1433x; 1.0467x over previous
#include <cuda_runtime.h>
#include <math.h>
#include <cstdint>

// Problem constants
#define B_    4
#define NLAT  512
#define NCTX  4096
#define MTOT  4608
#define DIM_  512
#define H_    8
#define DH_   64
#define DI_   512
#define SPLIT 4
#define SEGK  (MTOT / SPLIT)  // 1152 keys per split
#define NT_   (SEGK / 64)     // 18 tiles per split

// Scratch (allocation-free per harness rules)
__device__ float g_xt  [(size_t)B_ * NLAT * DIM_];
__device__ float g_ctxt[(size_t)B_ * NCTX * DIM_];
__device__ float g_wqt [(size_t)DI_ * DIM_];
__device__ float g_wkvt[(size_t)2 * DI_ * DIM_];
__device__ float g_wrep[(size_t)DIM_ * 1024];          // Wout replicated (hi|lo K)
__device__ float g_Q   [(size_t)B_ * NLAT * DI_];
__device__ float g_K   [(size_t)B_ * MTOT * DI_];      // K, row-major [m][512]
__device__ float g_V2  [(size_t)B_ * (MTOT/2) * 1024]; // V pair-interleaved
__device__ float g_O2  [(size_t)B_ * NLAT * 1024];     // attention out, hi|lo
__device__ float g_PO  [(size_t)B_ * H_ * 4 * SPLIT * 128 * 64];
__device__ float g_PM  [(size_t)B_ * H_ * 4 * SPLIT * 128];
__device__ float g_PL  [(size_t)B_ * H_ * 4 * SPLIT * 128];

// ---------------------------------------------------------------------------
// Helpers
// ---------------------------------------------------------------------------
__device__ __forceinline__ uint32_t f2t(float f) {
    uint32_t r;
    asm("cvt.rna.tf32.f32 %0, %1;" : "=r"(r) : "f"(f));
    return r;
}
__device__ __forceinline__ float f2tf(float f) { return __uint_as_float(f2t(f)); }
__device__ __forceinline__ uint32_t smem_u32(const void* p) {
    uint32_t a;
    asm("{ .reg .u64 t; cvta.to.shared.u64 t, %1; cvt.u32.u64 %0, t; }"
        : "=r"(a) : "l"(p));
    return a;
}
__device__ __forceinline__ void cpa16(uint32_t dst, const void* src) {
    asm volatile("cp.async.cg.shared.global [%0], [%1], 16;" :: "r"(dst), "l"(src));
}
#define CPA_COMMIT() asm volatile("cp.async.commit_group;" ::: "memory")
#define CPA_WAIT(n)  asm volatile("cp.async.wait_group %0;" :: "n"(n) : "memory")

#define MMA_TF32(C, A0, A1, A2, A3, B0, B1) \
    asm volatile("mma.sync.aligned.m16n8k8.row.col.f32.tf32.tf32.f32 " \
        "{%0,%1,%2,%3}, {%4,%5,%6,%7}, {%8,%9}, {%0,%1,%2,%3};" \
        : "+f"((C)[0]), "+f"((C)[1]), "+f"((C)[2]), "+f"((C)[3]) \
        : "r"(A0), "r"(A1), "r"(A2), "r"(A3), "r"(B0), "r"(B1))

// ===========================================================================
// Prep: round inputs to tf32 once. Wq folded with 0.125*log2(e). Wout
// replicated into [512][1024] (same 512 weights in both K-halves).
// ===========================================================================
#define NP4_X   ((size_t)B_ * NLAT * DIM_ / 4)
#define NP4_C   ((size_t)B_ * NCTX * DIM_ / 4)
#define NP4_Q   ((size_t)DI_ * DIM_ / 4)
#define NP4_K   ((size_t)2 * DI_ * DIM_ / 4)
#define NP4_W   ((size_t)DIM_ * 1024 / 4)
#define NP4_TOT (NP4_X + NP4_C + NP4_Q + NP4_K + NP4_W)

__global__ __launch_bounds__(256) void prep_round(
    const float* __restrict__ x, const float* __restrict__ ctx,
    const float* __restrict__ Wq, const float* __restrict__ Wkv,
    const float* __restrict__ Wout)
{
    size_t i = (size_t)blockIdx.x * 256 + threadIdx.x;

    const float* src; float* dst; float s = 1.f;
    if (i < NP4_X)                { src = x;   dst = g_xt; }
    else if ((i -= NP4_X) < NP4_C){ src = ctx; dst = g_ctxt; }
    else if ((i -= NP4_C) < NP4_Q){ src = Wq;  dst = g_wqt; s = 0.18033688011112042f; }
    else if ((i -= NP4_Q) < NP4_K){ src = Wkv; dst = g_wkvt; }
    else if ((i -= NP4_K) < NP4_W){
        // wrep[c][k] = round(Wout[c][k & 511])
        size_t wi = 4 * i;
        int c = (int)(wi >> 10), k = (int)(wi & 1023);
        float4 v = *(const float4*)(Wout + (size_t)c * DIM_ + (k & 511));
        *(float4*)(g_wrep + wi) = make_float4(f2tf(v.x), f2tf(v.y), f2tf(v.z), f2tf(v.w));
        return;
    } else return;

    float4 v = *(const float4*)(src + 4 * i);
    *(float4*)(dst + 4 * i) = make_float4(f2tf(v.x * s), f2tf(v.y * s),
                                          f2tf(v.z * s), f2tf(v.w * s));
}

// ===========================================================================
// Fused tf32 GEMM (NT), 3-stage cp.async, CTA 128x128, 8 warps (64x32).
// mode 0: dual launch — blocks [0,288) per batch: KV-proj (K epilogue for
//         cols<512, pair-interleaved V2 epilogue for cols>=512);
//         blocks [288,304): Q-proj.
// mode 1: out-proj — A = g_O2 (K=1024 hi|lo), W = g_wrep, C = outp (no round).
// ===========================================================================
#define GEMM_SMEM (3 * 8192 * 4)

__global__ void __launch_bounds__(256, 2) gemm_fused(int mode, float* __restrict__ outp)
{
    extern __shared__ uint32_t sm[];
    const uint32_t smb = smem_u32(sm);

    const int tid = threadIdx.x, w = tid >> 5, lane = tid & 31;
    const int g = lane >> 2, kq = lane & 3;
    const int b = blockIdx.z;
    const int wm = (w >> 2) * 64, wn = (w & 3) * 32;

    int rowBase, colBase, K, n1, epi;       // epi: 0=KV, 1=Q, 2=out
    const float *A1, *A2, *Wp;
    if (mode == 0) {
        const int bx = blockIdx.x;
        A1 = g_xt + (size_t)b * NLAT * DIM_;
        if (bx < 288) {
            colBase = (bx & 7) * 128; rowBase = (bx >> 3) * 128;
            n1 = NLAT; A2 = g_ctxt + (size_t)b * NCTX * DIM_;
            Wp = g_wkvt; K = 512; epi = 0;
        } else {
            const int q = bx - 288;
            colBase = (q & 3) * 128; rowBase = (q >> 2) * 128;
            n1 = 1 << 30; A2 = A1; Wp = g_wqt; K = 512; epi = 1;
        }
    } else {
        colBase = blockIdx.x * 128; rowBase = blockIdx.y * 128;
        A1 = g_O2 + (size_t)b * NLAT * 1024;
        n1 = 1 << 30; A2 = A1; Wp = g_wrep; K = 1024; epi = 2;
    }

    float c[4][4][4];
#pragma unroll
    for (int mt = 0; mt < 4; mt++)
#pragma unroll
        for (int nt = 0; nt < 4; nt++)
#pragma unroll
            for (int j = 0; j < 4; j++) c[mt][nt][j] = 0.f;

    auto issue = [&](int kt, int stage) {
        const int k0 = kt * 32;
        const uint32_t base = smb + stage * 8192 * 4;
#pragma unroll
        for (int i = 0; i < 4; i++) {
            int idx = tid + i * 256;
            int r = idx >> 3, ch = idx & 7;
            int grow = rowBase + r;
            const float* srcA = ((grow < n1) ? (A1 + (size_t)grow * K)
                                             : (A2 + (size_t)(grow - n1) * K)) + k0 + ch * 4;
            uint32_t dA = base + (uint32_t)((r * 32 + ((ch * 4) ^ ((r & 3) << 3))) << 2);
            cpa16(dA, srcA);
            const float* srcB = Wp + (size_t)(colBase + r) * K + k0 + ch * 4;
            cpa16(dA + 4096 * 4, srcB);
        }
    };

    issue(0, 0); CPA_COMMIT();
    issue(1, 1); CPA_COMMIT();

    const int KT = K >> 5;
    for (int kt = 0; kt < KT; ++kt) {
        if (kt == KT - 1) { CPA_WAIT(0); } else { CPA_WAIT(1); }
        __syncthreads();
        if (kt + 2 < KT) { issue(kt + 2, (kt + 2) % 3); CPA_COMMIT(); }

        const uint32_t* sA = sm + (kt % 3) * 8192;
        const uint32_t* sB = sA + 4096;
#pragma unroll
        for (int ks = 0; ks < 4; ++ks) {
            uint32_t a[4][4], bf[4][2];
            const int colw = (8 * ks + 2 * kq) ^ ((g & 3) << 3);
#pragma unroll
            for (int mt = 0; mt < 4; mt++) {
                int r0 = wm + mt * 16 + g;
                uint2 ua = *(const uint2*)&sA[r0 * 32 + colw];
                uint2 ub = *(const uint2*)&sA[(r0 + 8) * 32 + colw];
                a[mt][0] = ua.x; a[mt][1] = ub.x;
                a[mt][2] = ua.y; a[mt][3] = ub.y;
            }
#pragma unroll
            for (int nt = 0; nt < 4; nt++) {
                uint2 vb = *(const uint2*)&sB[(wn + nt * 8 + g) * 32 + colw];
                bf[nt][0] = vb.x; bf[nt][1] = vb.y;
            }
#pragma unroll
            for (int mt = 0; mt < 4; mt++)
#pragma unroll
                for (int nt = 0; nt < 4; nt++)
                    MMA_TF32(c[mt][nt], a[mt][0], a[mt][1], a[mt][2], a[mt][3],
                             bf[nt][0], bf[nt][1]);
        }
    }

    // ---- epilogue
    const int isV = (epi == 0) && (colBase >= 512);
#pragma unroll
    for (int mt = 0; mt < 4; mt++) {
        int row0 = rowBase + wm + mt * 16 + g;
#pragma unroll
        for (int nt = 0; nt < 4; nt++) {
            int col = colBase + wn + nt * 8 + 2 * kq;
            float v0 = c[mt][nt][0], v1 = c[mt][nt][1];
            float v2 = c[mt][nt][2], v3 = c[mt][nt][3];
            if (epi == 2) {
                *(float2*)&outp[((size_t)b * NLAT + row0) * DIM_ + col] = make_float2(v0, v1);
                *(float2*)&outp[((size_t)b * NLAT + row0 + 8) * DIM_ + col] = make_float2(v2, v3);
            } else if (epi == 1) {
                *(float2*)&g_Q[((size_t)b * NLAT + row0) * DI_ + col] =
                    make_float2(f2tf(v0), f2tf(v1));
                *(float2*)&g_Q[((size_t)b * NLAT + row0 + 8) * DI_ + col] =
                    make_float2(f2tf(v2), f2tf(v3));
            } else if (!isV) {
                *(float2*)&g_K[((size_t)b * MTOT + row0) * DI_ + col] =
                    make_float2(f2tf(v0), f2tf(v1));
                *(float2*)&g_K[((size_t)b * MTOT + row0 + 8) * DI_ + col] =
                    make_float2(f2tf(v2), f2tf(v3));
            } else {
                // V2: [b][pair][h*128 + 2*dh + (key&1)]
                int d = col - 512, hh = d >> 6, dh = d & 63;
                size_t pb = (size_t)b * (MTOT / 2);
                size_t a1 = (pb + (row0 >> 1)) * 1024 + hh * 128 + 2 * dh + (row0 & 1);
                size_t a2 = (pb + ((row0 + 8) >> 1)) * 1024 + hh * 128 + 2 * dh + ((row0 + 8) & 1);
                g_V2[a1] = f2tf(v0); g_V2[a1 + 2] = f2tf(v1);
                g_V2[a2] = f2tf(v2); g_V2[a2 + 2] = f2tf(v3);
            }
        }
    }
}

// ===========================================================================
// Flash attention, split-K by 4, 3-stage cp.async, tf32 mma.
// K smem rows padded to 72 (LDS.64 b-frags). V smem pair-interleaved:
// sV[pair][2*d + key&1], pair stride 136 words -> PV b-frags are LDS.64
// (bank index 4kq+g, conflict-free). P C-fragment reused as PV A-fragment.
// ===========================================================================
#define KPAD 72
#define VP2  136
#define STG_W (64 * KPAD + 32 * VP2)       // 8960 words per stage
#define ATT_SMEM (3 * STG_W * 4)           // 107520 B

__global__ void __launch_bounds__(256, 2) attn_ca(void)
{
    extern __shared__ uint32_t sm[];
    const uint32_t smb = smem_u32(sm);

    const int qt = blockIdx.x, h = blockIdx.y;
    const int b = blockIdx.z >> 2, sp = blockIdx.z & 3;
    const int tid = threadIdx.x, w = tid >> 5, lane = tid & 31;
    const int g = lane >> 2, kq = lane & 3;

    const float* kB  = g_K  + ((size_t)b * MTOT + sp * SEGK) * DI_ + h * DH_;
    const float* v2B = g_V2 + ((size_t)b * (MTOT/2) + sp * (SEGK/2)) * 1024 + h * 128;

    auto issue = [&](int t) {
        const uint32_t base = smb + (uint32_t)((t % 3) * STG_W * 4);
        {   // K tile: 64 rows x 64 words
            int idx = tid;
#pragma unroll
            for (int i = 0; i < 4; i++, idx += 256) {
                int r = idx >> 4, c = idx & 15;
                cpa16(base + (uint32_t)((r * KPAD + c * 4) << 2),
                      kB + (size_t)(t * 64 + r) * DI_ + c * 4);
            }
        }
        {   // V tile: 32 pair-rows x 128 words
            int idx = tid;
#pragma unroll
            for (int i = 0; i < 4; i++, idx += 256) {
                int p = idx >> 5, c = idx & 31;
                cpa16(base + (uint32_t)((64 * KPAD + p * VP2 + c * 4) << 2),
                      v2B + (size_t)(t * 32 + p) * 1024 + c * 4);
            }
        }
    };

    issue(0); CPA_COMMIT();
    issue(1); CPA_COMMIT();

    // ---- stage Q tile into stage-2 region (overlaps with cp.async)
    uint32_t* qs = sm + 2 * STG_W;
    {
        const float* qsrc = g_Q + ((size_t)(b * NLAT + qt * 128)) * DI_ + h * DH_;
#pragma unroll
        for (int i = 0; i < 8; i++) {
            int idx = tid + i * 256;
            int r = idx >> 4, c4 = idx & 15;
            float4 v = *(const float4*)(qsrc + (size_t)r * DI_ + c4 * 4);
            *(float4*)(qs + r * 68 + c4 * 4) = v;
        }
    }
    __syncthreads();

    uint32_t qf[8][4];
    {
        const int r0 = w * 16 + g;
#pragma unroll
        for (int s = 0; s < 8; s++) {
            uint2 u0 = *(const uint2*)&qs[r0 * 68 + 8 * s + 2 * kq];
            uint2 u1 = *(const uint2*)&qs[(r0 + 8) * 68 + 8 * s + 2 * kq];
            qf[s][0] = u0.x; qf[s][1] = u1.x;
            qf[s][2] = u0.y; qf[s][3] = u1.y;
        }
    }

    float o[8][4];
#pragma unroll
    for (int dt = 0; dt < 8; dt++)
#pragma unroll
        for (int j = 0; j < 4; j++) o[dt][j] = 0.f;
    float mA = -INFINITY, mB = -INFINITY, lA = 0.f, lB = 0.f;

    for (int t = 0; t < NT_; ++t) {
        if (t == NT_ - 1) { CPA_WAIT(0); } else { CPA_WAIT(1); }
        __syncthreads();
        if (t + 2 < NT_) { issue(t + 2); CPA_COMMIT(); }

        const uint32_t* sK = sm + (t % 3) * STG_W;
        const uint32_t* sV = sK + 64 * KPAD;

        // ---- S = Q K^T (log2 domain)
        float s[8][4];
#pragma unroll
        for (int nt = 0; nt < 8; nt++)
#pragma unroll
            for (int j = 0; j < 4; j++) s[nt][j] = 0.f;
#pragma unroll
        for (int ks = 0; ks < 8; ks++) {
            const int dcol = 8 * ks + 2 * kq;
#pragma unroll
            for (int nt = 0; nt < 8; nt++) {
                uint2 kb = *(const uint2*)&sK[(8 * nt + g) * KPAD + dcol];
                MMA_TF32(s[nt], qf[ks][0], qf[ks][1], qf[ks][2], qf[ks][3],
                         kb.x, kb.y);
            }
        }

        // ---- online softmax (exp2)
        float tA = -INFINITY, tB = -INFINITY;
#pragma unroll
        for (int nt = 0; nt < 8; nt++) {
            tA = fmaxf(tA, fmaxf(s[nt][0], s[nt][1]));
            tB = fmaxf(tB, fmaxf(s[nt][2], s[nt][3]));
        }
        tA = fmaxf(tA, __shfl_xor_sync(0xffffffffu, tA, 1));
        tA = fmaxf(tA, __shfl_xor_sync(0xffffffffu, tA, 2));
        tB = fmaxf(tB, __shfl_xor_sync(0xffffffffu, tB, 1));
        tB = fmaxf(tB, __shfl_xor_sync(0xffffffffu, tB, 2));

        float mnA = fmaxf(mA, tA), mnB = fmaxf(mB, tB);
        float scA = exp2f(mA - mnA), scB = exp2f(mB - mnB);
        mA = mnA; mB = mnB;

        float suA = 0.f, suB = 0.f;
#pragma unroll
        for (int nt = 0; nt < 8; nt++) {
            s[nt][0] = exp2f(s[nt][0] - mnA); suA += s[nt][0];
            s[nt][1] = exp2f(s[nt][1] - mnA); suA += s[nt][1];
            s[nt][2] = exp2f(s[nt][2] - mnB); suB += s[nt][2];
            s[nt][3] = exp2f(s[nt][3] - mnB); suB += s[nt][3];
        }
        suA += __shfl_xor_sync(0xffffffffu, suA, 1);
        suA += __shfl_xor_sync(0xffffffffu, suA, 2);
        suB += __shfl_xor_sync(0xffffffffu, suB, 1);
        suB += __shfl_xor_sync(0xffffffffu, suB, 2);
        lA = lA * scA + suA;
        lB = lB * scB + suB;

        if (__any_sync(0xffffffffu, (scA != 1.f) || (scB != 1.f))) {
#pragma unroll
            for (int dt = 0; dt < 8; dt++) {
                o[dt][0] *= scA; o[dt][1] *= scA;
                o[dt][2] *= scB; o[dt][3] *= scB;
            }
        }

        // ---- O += P V : C-frag as A-frag, V b-frags via LDS.64
#pragma unroll
        for (int ks = 0; ks < 8; ks++) {
            uint32_t a0 = __float_as_uint(s[ks][0]);
            uint32_t a1 = __float_as_uint(s[ks][2]);
            uint32_t a2 = __float_as_uint(s[ks][1]);
            uint32_t a3 = __float_as_uint(s[ks][3]);
            const uint32_t* vrow = sV + (4 * ks + kq) * VP2 + 2 * g;
#pragma unroll
            for (int dt = 0; dt < 8; dt++) {
                uint2 vb = *(const uint2*)&vrow[16 * dt];
                MMA_TF32(o[dt], a0, a1, a2, a3, vb.x, vb.y);
            }
        }
    }

    // ---- store unnormalized partials + (m, l)
    const int pidx = (((b * H_ + h) * 4 + qt) * SPLIT + sp);
    float* pob = g_PO + (size_t)pidx * 128 * 64;
    const int r0 = w * 16 + g;
#pragma unroll
    for (int dt = 0; dt < 8; dt++) {
        *(float2*)&pob[r0 * 64 + 8 * dt + 2 * kq]       = make_float2(o[dt][0], o[dt][1]);
        *(float2*)&pob[(r0 + 8) * 64 + 8 * dt + 2 * kq] = make_float2(o[dt][2], o[dt][3]);
    }
    if (kq == 0) {
        g_PM[pidx * 128 + r0]     = mA; g_PM[pidx * 128 + r0 + 8] = mB;
        g_PL[pidx * 128 + r0]     = lA; g_PL[pidx * 128 + r0 + 8] = lB;
    }
}

// ===========================================================================
// Merge split-K partials -> O2 (tf32 hi | lo halves, K=1024 for out-proj)
// ===========================================================================
__global__ __launch_bounds__(256) void merge_k(void)
{
    const int qt = blockIdx.x, h = blockIdx.y, b = blockIdx.z;
    const int tid = threadIdx.x;
    const int row = tid >> 1, colh = (tid & 1) * 32;
    const int base = ((b * H_ + h) * 4 + qt) * SPLIT;

    float m[SPLIT], l[SPLIT];
#pragma unroll
    for (int s = 0; s < SPLIT; s++) {
        m[s] = g_PM[(base + s) * 128 + row];
        l[s] = g_PL[(base + s) * 128 + row];
    }
    float M = fmaxf(fmaxf(m[0], m[1]), fmaxf(m[2], m[3]));
    float wgt[SPLIT], L = 0.f;
#pragma unroll
    for (int s = 0; s < SPLIT; s++) { wgt[s] = exp2f(m[s] - M); L += wgt[s] * l[s]; }
    const float inv = 1.f / L;
#pragma unroll
    for (int s = 0; s < SPLIT; s++) wgt[s] *= inv;

    float* op = g_O2 + ((size_t)(b * NLAT + qt * 128 + row)) * 1024 + h * DH_ + colh;
#pragma unroll
    for (int j = 0; j < 8; j++) {
        float4 acc = make_float4(0.f, 0.f, 0.f, 0.f);
#pragma unroll
        for (int s = 0; s < SPLIT; s++) {
            float4 v = *(const float4*)&g_PO[((size_t)(base + s) * 128 + row) * 64 + colh + 4 * j];
            acc.x += wgt[s] * v.x; acc.y += wgt[s] * v.y;
            acc.z += wgt[s] * v.z; acc.w += wgt[s] * v.w;
        }
        float4 hi = make_float4(f2tf(acc.x), f2tf(acc.y), f2tf(acc.z), f2tf(acc.w));
        float4 lo = make_float4(f2tf(acc.x - hi.x), f2tf(acc.y - hi.y),
                                f2tf(acc.z - hi.z), f2tf(acc.w - hi.w));
        *(float4*)(op + 4 * j)       = hi;
        *(float4*)(op + 512 + 4 * j) = lo;
    }
}

// ===========================================================================
// Launch
// ===========================================================================
extern "C" void kernel_launch(void* const* d_in, const int* in_sizes, int n_in,
                              void* d_out, int out_size)
{
    const float* x    = (const float*)d_in[0];
    const float* ctx  = (const float*)d_in[1];
    const float* Wq   = (const float*)d_in[2];
    const float* Wkv  = (const float*)d_in[3];
    const float* Wout = (const float*)d_in[4];
    float* out = (float*)d_out;

    cudaFuncSetAttribute(gemm_fused, cudaFuncAttributeMaxDynamicSharedMemorySize, GEMM_SMEM);
    cudaFuncSetAttribute(attn_ca,    cudaFuncAttributeMaxDynamicSharedMemorySize, ATT_SMEM);

    // 0. round inputs to tf32 (+ fold scale into Wq, replicate Wout)
    prep_round<<<(unsigned)((NP4_TOT + 255) / 256), 256>>>(x, ctx, Wq, Wkv, Wout);

    // 1. KV-proj (K + pair-interleaved V2) fused with Q-proj
    gemm_fused<<<dim3(304, 1, B_), 256, GEMM_SMEM>>>(0, nullptr);

    // 2. attention partials (split-K by 4)
    attn_ca<<<dim3(NLAT / 128, H_, B_ * SPLIT), 256, ATT_SMEM>>>();

    // 3. merge partials -> O2 (hi|lo)
    merge_k<<<dim3(NLAT / 128, H_, B_), 256>>>();

    // 4. out = (Ohi + Olo) @ Wout^T  (K=1024 pipelined gemm)
    gemm_fused<<<dim3(DIM_ / 128, NLAT / 128, B_), 256, GEMM_SMEM>>>(1, out);
}

// round 7
// speedup vs baseline: 6.4065x; 1.0428x over previous
#include <cuda_runtime.h>
#include <math.h>
#include <cstdint>

// Problem constants
#define B_    4
#define NLAT  512
#define NCTX  4096
#define MTOT  4608
#define DIM_  512
#define H_    8
#define DH_   64
#define DI_   512
#define SPLIT 2
#define SEGK  (MTOT / SPLIT)  // 2304 keys per split
#define NT_   (SEGK / 64)     // 36 tiles per split

// Scratch (allocation-free per harness rules)
__device__ float g_xt  [(size_t)B_ * NLAT * DIM_];
__device__ float g_ctxt[(size_t)B_ * NCTX * DIM_];
__device__ float g_wqt [(size_t)DI_ * DIM_];
__device__ float g_wkvt[(size_t)2 * DI_ * DIM_];
__device__ float g_wrep[(size_t)DIM_ * 1024];          // Wout replicated (hi|lo K)
__device__ float g_Q   [(size_t)B_ * NLAT * DI_];
__device__ float g_K   [(size_t)B_ * MTOT * DI_];      // K, row-major [m][512]
__device__ float g_V2  [(size_t)B_ * (MTOT/2) * 1024]; // V pair-interleaved
__device__ float g_O2  [(size_t)B_ * NLAT * 1024];     // attention out, hi|lo
__device__ float g_PO  [(size_t)B_ * H_ * 4 * SPLIT * 128 * 64];
__device__ float g_PM  [(size_t)B_ * H_ * 4 * SPLIT * 128];
__device__ float g_PL  [(size_t)B_ * H_ * 4 * SPLIT * 128];

// ---------------------------------------------------------------------------
// Helpers
// ---------------------------------------------------------------------------
__device__ __forceinline__ uint32_t f2t(float f) {
    uint32_t r;
    asm("cvt.rna.tf32.f32 %0, %1;" : "=r"(r) : "f"(f));
    return r;
}
__device__ __forceinline__ float f2tf(float f) { return __uint_as_float(f2t(f)); }
__device__ __forceinline__ uint32_t smem_u32(const void* p) {
    uint32_t a;
    asm("{ .reg .u64 t; cvta.to.shared.u64 t, %1; cvt.u32.u64 %0, t; }"
        : "=r"(a) : "l"(p));
    return a;
}
__device__ __forceinline__ void cpa16(uint32_t dst, const void* src) {
    asm volatile("cp.async.cg.shared.global [%0], [%1], 16;" :: "r"(dst), "l"(src));
}
#define CPA_COMMIT() asm volatile("cp.async.commit_group;" ::: "memory")
#define CPA_WAIT(n)  asm volatile("cp.async.wait_group %0;" :: "n"(n) : "memory")

#define MMA_TF32(C, A0, A1, A2, A3, B0, B1) \
    asm volatile("mma.sync.aligned.m16n8k8.row.col.f32.tf32.tf32.f32 " \
        "{%0,%1,%2,%3}, {%4,%5,%6,%7}, {%8,%9}, {%0,%1,%2,%3};" \
        : "+f"((C)[0]), "+f"((C)[1]), "+f"((C)[2]), "+f"((C)[3]) \
        : "r"(A0), "r"(A1), "r"(A2), "r"(A3), "r"(B0), "r"(B1))

// ===========================================================================
// Prep: round inputs to tf32 once. Wq folded with 0.125*log2(e). Wout
// replicated into [512][1024] (same 512 weights in both K-halves).
// ===========================================================================
#define NP4_X   ((size_t)B_ * NLAT * DIM_ / 4)
#define NP4_C   ((size_t)B_ * NCTX * DIM_ / 4)
#define NP4_Q   ((size_t)DI_ * DIM_ / 4)
#define NP4_K   ((size_t)2 * DI_ * DIM_ / 4)
#define NP4_W   ((size_t)DIM_ * 1024 / 4)
#define NP4_TOT (NP4_X + NP4_C + NP4_Q + NP4_K + NP4_W)

__global__ __launch_bounds__(256) void prep_round(
    const float* __restrict__ x, const float* __restrict__ ctx,
    const float* __restrict__ Wq, const float* __restrict__ Wkv,
    const float* __restrict__ Wout)
{
    size_t i = (size_t)blockIdx.x * 256 + threadIdx.x;

    const float* src; float* dst; float s = 1.f;
    if (i < NP4_X)                { src = x;   dst = g_xt; }
    else if ((i -= NP4_X) < NP4_C){ src = ctx; dst = g_ctxt; }
    else if ((i -= NP4_C) < NP4_Q){ src = Wq;  dst = g_wqt; s = 0.18033688011112042f; }
    else if ((i -= NP4_Q) < NP4_K){ src = Wkv; dst = g_wkvt; }
    else if ((i -= NP4_K) < NP4_W){
        size_t wi = 4 * i;
        int c = (int)(wi >> 10), k = (int)(wi & 1023);
        float4 v = *(const float4*)(Wout + (size_t)c * DIM_ + (k & 511));
        *(float4*)(g_wrep + wi) = make_float4(f2tf(v.x), f2tf(v.y), f2tf(v.z), f2tf(v.w));
        return;
    } else return;

    float4 v = *(const float4*)(src + 4 * i);
    *(float4*)(dst + 4 * i) = make_float4(f2tf(v.x * s), f2tf(v.y * s),
                                          f2tf(v.z * s), f2tf(v.w * s));
}

// ===========================================================================
// Fused tf32 GEMM (NT), 3-stage cp.async, CTA 128x128, 8 warps (64x32).
// mode 0: blocks [0,288): KV-proj (K / pair-interleaved V2 epilogues);
//         blocks [288,304): Q-proj.
// mode 1: out-proj — A = g_O2 (K=1024 hi|lo), W = g_wrep, C = outp.
// ===========================================================================
#define GEMM_SMEM (3 * 8192 * 4)

__global__ void __launch_bounds__(256, 2) gemm_fused(int mode, float* __restrict__ outp)
{
    extern __shared__ uint32_t sm[];
    const uint32_t smb = smem_u32(sm);

    const int tid = threadIdx.x, w = tid >> 5, lane = tid & 31;
    const int g = lane >> 2, kq = lane & 3;
    const int b = blockIdx.z;
    const int wm = (w >> 2) * 64, wn = (w & 3) * 32;

    int rowBase, colBase, K, n1, epi;       // epi: 0=KV, 1=Q, 2=out
    const float *A1, *A2, *Wp;
    if (mode == 0) {
        const int bx = blockIdx.x;
        A1 = g_xt + (size_t)b * NLAT * DIM_;
        if (bx < 288) {
            colBase = (bx & 7) * 128; rowBase = (bx >> 3) * 128;
            n1 = NLAT; A2 = g_ctxt + (size_t)b * NCTX * DIM_;
            Wp = g_wkvt; K = 512; epi = 0;
        } else {
            const int q = bx - 288;
            colBase = (q & 3) * 128; rowBase = (q >> 2) * 128;
            n1 = 1 << 30; A2 = A1; Wp = g_wqt; K = 512; epi = 1;
        }
    } else {
        colBase = blockIdx.x * 128; rowBase = blockIdx.y * 128;
        A1 = g_O2 + (size_t)b * NLAT * 1024;
        n1 = 1 << 30; A2 = A1; Wp = g_wrep; K = 1024; epi = 2;
    }

    float c[4][4][4];
#pragma unroll
    for (int mt = 0; mt < 4; mt++)
#pragma unroll
        for (int nt = 0; nt < 4; nt++)
#pragma unroll
            for (int j = 0; j < 4; j++) c[mt][nt][j] = 0.f;

    auto issue = [&](int kt, int stage) {
        const int k0 = kt * 32;
        const uint32_t base = smb + stage * 8192 * 4;
#pragma unroll
        for (int i = 0; i < 4; i++) {
            int idx = tid + i * 256;
            int r = idx >> 3, ch = idx & 7;
            int grow = rowBase + r;
            const float* srcA = ((grow < n1) ? (A1 + (size_t)grow * K)
                                             : (A2 + (size_t)(grow - n1) * K)) + k0 + ch * 4;
            uint32_t dA = base + (uint32_t)((r * 32 + ((ch * 4) ^ ((r & 3) << 3))) << 2);
            cpa16(dA, srcA);
            const float* srcB = Wp + (size_t)(colBase + r) * K + k0 + ch * 4;
            cpa16(dA + 4096 * 4, srcB);
        }
    };

    issue(0, 0); CPA_COMMIT();
    issue(1, 1); CPA_COMMIT();

    const int KT = K >> 5;
    for (int kt = 0; kt < KT; ++kt) {
        if (kt == KT - 1) { CPA_WAIT(0); } else { CPA_WAIT(1); }
        __syncthreads();
        if (kt + 2 < KT) { issue(kt + 2, (kt + 2) % 3); CPA_COMMIT(); }

        const uint32_t* sA = sm + (kt % 3) * 8192;
        const uint32_t* sB = sA + 4096;
#pragma unroll
        for (int ks = 0; ks < 4; ++ks) {
            uint32_t a[4][4], bf[4][2];
            const int colw = (8 * ks + 2 * kq) ^ ((g & 3) << 3);
#pragma unroll
            for (int mt = 0; mt < 4; mt++) {
                int r0 = wm + mt * 16 + g;
                uint2 ua = *(const uint2*)&sA[r0 * 32 + colw];
                uint2 ub = *(const uint2*)&sA[(r0 + 8) * 32 + colw];
                a[mt][0] = ua.x; a[mt][1] = ub.x;
                a[mt][2] = ua.y; a[mt][3] = ub.y;
            }
#pragma unroll
            for (int nt = 0; nt < 4; nt++) {
                uint2 vb = *(const uint2*)&sB[(wn + nt * 8 + g) * 32 + colw];
                bf[nt][0] = vb.x; bf[nt][1] = vb.y;
            }
#pragma unroll
            for (int mt = 0; mt < 4; mt++)
#pragma unroll
                for (int nt = 0; nt < 4; nt++)
                    MMA_TF32(c[mt][nt], a[mt][0], a[mt][1], a[mt][2], a[mt][3],
                             bf[nt][0], bf[nt][1]);
        }
    }

    // ---- epilogue
    const int isV = (epi == 0) && (colBase >= 512);
#pragma unroll
    for (int mt = 0; mt < 4; mt++) {
        int row0 = rowBase + wm + mt * 16 + g;
#pragma unroll
        for (int nt = 0; nt < 4; nt++) {
            int col = colBase + wn + nt * 8 + 2 * kq;
            float v0 = c[mt][nt][0], v1 = c[mt][nt][1];
            float v2 = c[mt][nt][2], v3 = c[mt][nt][3];
            if (epi == 2) {
                *(float2*)&outp[((size_t)b * NLAT + row0) * DIM_ + col] = make_float2(v0, v1);
                *(float2*)&outp[((size_t)b * NLAT + row0 + 8) * DIM_ + col] = make_float2(v2, v3);
            } else if (epi == 1) {
                *(float2*)&g_Q[((size_t)b * NLAT + row0) * DI_ + col] =
                    make_float2(f2tf(v0), f2tf(v1));
                *(float2*)&g_Q[((size_t)b * NLAT + row0 + 8) * DI_ + col] =
                    make_float2(f2tf(v2), f2tf(v3));
            } else if (!isV) {
                *(float2*)&g_K[((size_t)b * MTOT + row0) * DI_ + col] =
                    make_float2(f2tf(v0), f2tf(v1));
                *(float2*)&g_K[((size_t)b * MTOT + row0 + 8) * DI_ + col] =
                    make_float2(f2tf(v2), f2tf(v3));
            } else {
                int d = col - 512, hh = d >> 6, dh = d & 63;
                size_t pb = (size_t)b * (MTOT / 2);
                size_t a1 = (pb + (row0 >> 1)) * 1024 + hh * 128 + 2 * dh + (row0 & 1);
                size_t a2 = (pb + ((row0 + 8) >> 1)) * 1024 + hh * 128 + 2 * dh + ((row0 + 8) & 1);
                g_V2[a1] = f2tf(v0); g_V2[a1 + 2] = f2tf(v1);
                g_V2[a2] = f2tf(v2); g_V2[a2 + 2] = f2tf(v3);
            }
        }
    }
}

// ===========================================================================
// Flash attention, split-K by 2 (single wave: 256 CTAs @ occ 2), 3-stage
// cp.async, tf32 mma. K rows padded to 72 (LDS.64); V pair-interleaved
// (stride 136, LDS.64). P C-fragment reused directly as PV A-fragment.
// ===========================================================================
#define KPAD 72
#define VP2  136
#define STG_W (64 * KPAD + 32 * VP2)       // 8960 words per stage
#define ATT_SMEM (3 * STG_W * 4)           // 107520 B

__global__ void __launch_bounds__(256, 2) attn_ca(void)
{
    extern __shared__ uint32_t sm[];
    const uint32_t smb = smem_u32(sm);

    const int qt = blockIdx.x, h = blockIdx.y;
    const int b = blockIdx.z >> 1, sp = blockIdx.z & 1;
    const int tid = threadIdx.x, w = tid >> 5, lane = tid & 31;
    const int g = lane >> 2, kq = lane & 3;

    const float* kB  = g_K  + ((size_t)b * MTOT + sp * SEGK) * DI_ + h * DH_;
    const float* v2B = g_V2 + ((size_t)b * (MTOT/2) + sp * (SEGK/2)) * 1024 + h * 128;

    auto issue = [&](int t) {
        const uint32_t base = smb + (uint32_t)((t % 3) * STG_W * 4);
        {
            int idx = tid;
#pragma unroll
            for (int i = 0; i < 4; i++, idx += 256) {
                int r = idx >> 4, c = idx & 15;
                cpa16(base + (uint32_t)((r * KPAD + c * 4) << 2),
                      kB + (size_t)(t * 64 + r) * DI_ + c * 4);
            }
        }
        {
            int idx = tid;
#pragma unroll
            for (int i = 0; i < 4; i++, idx += 256) {
                int p = idx >> 5, c = idx & 31;
                cpa16(base + (uint32_t)((64 * KPAD + p * VP2 + c * 4) << 2),
                      v2B + (size_t)(t * 32 + p) * 1024 + c * 4);
            }
        }
    };

    issue(0); CPA_COMMIT();
    issue(1); CPA_COMMIT();

    // ---- stage Q tile into stage-2 region (overlaps with cp.async)
    uint32_t* qs = sm + 2 * STG_W;
    {
        const float* qsrc = g_Q + ((size_t)(b * NLAT + qt * 128)) * DI_ + h * DH_;
#pragma unroll
        for (int i = 0; i < 8; i++) {
            int idx = tid + i * 256;
            int r = idx >> 4, c4 = idx & 15;
            float4 v = *(const float4*)(qsrc + (size_t)r * DI_ + c4 * 4);
            *(float4*)(qs + r * 68 + c4 * 4) = v;
        }
    }
    __syncthreads();

    uint32_t qf[8][4];
    {
        const int r0 = w * 16 + g;
#pragma unroll
        for (int s = 0; s < 8; s++) {
            uint2 u0 = *(const uint2*)&qs[r0 * 68 + 8 * s + 2 * kq];
            uint2 u1 = *(const uint2*)&qs[(r0 + 8) * 68 + 8 * s + 2 * kq];
            qf[s][0] = u0.x; qf[s][1] = u1.x;
            qf[s][2] = u0.y; qf[s][3] = u1.y;
        }
    }

    float o[8][4];
#pragma unroll
    for (int dt = 0; dt < 8; dt++)
#pragma unroll
        for (int j = 0; j < 4; j++) o[dt][j] = 0.f;
    float mA = -INFINITY, mB = -INFINITY, lA = 0.f, lB = 0.f;

    for (int t = 0; t < NT_; ++t) {
        if (t == NT_ - 1) { CPA_WAIT(0); } else { CPA_WAIT(1); }
        __syncthreads();
        if (t + 2 < NT_) { issue(t + 2); CPA_COMMIT(); }

        const uint32_t* sK = sm + (t % 3) * STG_W;
        const uint32_t* sV = sK + 64 * KPAD;

        // ---- S = Q K^T (log2 domain)
        float s[8][4];
#pragma unroll
        for (int nt = 0; nt < 8; nt++)
#pragma unroll
            for (int j = 0; j < 4; j++) s[nt][j] = 0.f;
#pragma unroll
        for (int ks = 0; ks < 8; ks++) {
            const int dcol = 8 * ks + 2 * kq;
#pragma unroll
            for (int nt = 0; nt < 8; nt++) {
                uint2 kb = *(const uint2*)&sK[(8 * nt + g) * KPAD + dcol];
                MMA_TF32(s[nt], qf[ks][0], qf[ks][1], qf[ks][2], qf[ks][3],
                         kb.x, kb.y);
            }
        }

        // ---- online softmax (exp2), ILP-4 reductions
        float xA0, xA1, xA2, xA3, xB0, xB1, xB2, xB3;
        xA0 = fmaxf(s[0][0], s[0][1]); xA1 = fmaxf(s[1][0], s[1][1]);
        xA2 = fmaxf(s[2][0], s[2][1]); xA3 = fmaxf(s[3][0], s[3][1]);
        xB0 = fmaxf(s[0][2], s[0][3]); xB1 = fmaxf(s[1][2], s[1][3]);
        xB2 = fmaxf(s[2][2], s[2][3]); xB3 = fmaxf(s[3][2], s[3][3]);
#pragma unroll
        for (int nt = 4; nt < 8; nt++) {
            float* xa = (nt == 4) ? &xA0 : (nt == 5) ? &xA1 : (nt == 6) ? &xA2 : &xA3;
            float* xb = (nt == 4) ? &xB0 : (nt == 5) ? &xB1 : (nt == 6) ? &xB2 : &xB3;
            *xa = fmaxf(*xa, fmaxf(s[nt][0], s[nt][1]));
            *xb = fmaxf(*xb, fmaxf(s[nt][2], s[nt][3]));
        }
        float tA = fmaxf(fmaxf(xA0, xA1), fmaxf(xA2, xA3));
        float tB = fmaxf(fmaxf(xB0, xB1), fmaxf(xB2, xB3));
        tA = fmaxf(tA, __shfl_xor_sync(0xffffffffu, tA, 1));
        tA = fmaxf(tA, __shfl_xor_sync(0xffffffffu, tA, 2));
        tB = fmaxf(tB, __shfl_xor_sync(0xffffffffu, tB, 1));
        tB = fmaxf(tB, __shfl_xor_sync(0xffffffffu, tB, 2));

        float mnA = fmaxf(mA, tA), mnB = fmaxf(mB, tB);
        float scA = exp2f(mA - mnA), scB = exp2f(mB - mnB);
        mA = mnA; mB = mnB;

        float a0 = 0.f, a1 = 0.f, a2 = 0.f, a3 = 0.f;
        float b0 = 0.f, b1 = 0.f, b2 = 0.f, b3 = 0.f;
#pragma unroll
        for (int nt = 0; nt < 8; nt++) {
            s[nt][0] = exp2f(s[nt][0] - mnA);
            s[nt][1] = exp2f(s[nt][1] - mnA);
            s[nt][2] = exp2f(s[nt][2] - mnB);
            s[nt][3] = exp2f(s[nt][3] - mnB);
        }
#pragma unroll
        for (int nt = 0; nt < 8; nt += 2) {
            a0 += s[nt][0];   a1 += s[nt][1];
            a2 += s[nt+1][0]; a3 += s[nt+1][1];
            b0 += s[nt][2];   b1 += s[nt][3];
            b2 += s[nt+1][2]; b3 += s[nt+1][3];
        }
        float suA = (a0 + a1) + (a2 + a3);
        float suB = (b0 + b1) + (b2 + b3);
        suA += __shfl_xor_sync(0xffffffffu, suA, 1);
        suA += __shfl_xor_sync(0xffffffffu, suA, 2);
        suB += __shfl_xor_sync(0xffffffffu, suB, 1);
        suB += __shfl_xor_sync(0xffffffffu, suB, 2);
        lA = lA * scA + suA;
        lB = lB * scB + suB;

        if (__any_sync(0xffffffffu, (scA != 1.f) || (scB != 1.f))) {
#pragma unroll
            for (int dt = 0; dt < 8; dt++) {
                o[dt][0] *= scA; o[dt][1] *= scA;
                o[dt][2] *= scB; o[dt][3] *= scB;
            }
        }

        // ---- O += P V : C-frag as A-frag, V b-frags via LDS.64
#pragma unroll
        for (int ks = 0; ks < 8; ks++) {
            uint32_t p0 = __float_as_uint(s[ks][0]);
            uint32_t p1 = __float_as_uint(s[ks][2]);
            uint32_t p2 = __float_as_uint(s[ks][1]);
            uint32_t p3 = __float_as_uint(s[ks][3]);
            const uint32_t* vrow = sV + (4 * ks + kq) * VP2 + 2 * g;
#pragma unroll
            for (int dt = 0; dt < 8; dt++) {
                uint2 vb = *(const uint2*)&vrow[16 * dt];
                MMA_TF32(o[dt], p0, p1, p2, p3, vb.x, vb.y);
            }
        }
    }

    // ---- store unnormalized partials + (m, l)
    const int pidx = (((b * H_ + h) * 4 + qt) * SPLIT + sp);
    float* pob = g_PO + (size_t)pidx * 128 * 64;
    const int r0 = w * 16 + g;
#pragma unroll
    for (int dt = 0; dt < 8; dt++) {
        *(float2*)&pob[r0 * 64 + 8 * dt + 2 * kq]       = make_float2(o[dt][0], o[dt][1]);
        *(float2*)&pob[(r0 + 8) * 64 + 8 * dt + 2 * kq] = make_float2(o[dt][2], o[dt][3]);
    }
    if (kq == 0) {
        g_PM[pidx * 128 + r0]     = mA; g_PM[pidx * 128 + r0 + 8] = mB;
        g_PL[pidx * 128 + r0]     = lA; g_PL[pidx * 128 + r0 + 8] = lB;
    }
}

// ===========================================================================
// Merge split-K partials -> O2 (tf32 hi|lo). 256 blocks x 64 rows,
// 16 floats/thread: latency-parallel instead of 128 tiny blocks.
// ===========================================================================
__global__ __launch_bounds__(256) void merge_k(void)
{
    const int qt2 = blockIdx.x, h = blockIdx.y, b = blockIdx.z;
    const int qt = qt2 >> 1, rhalf = (qt2 & 1) * 64;
    const int tid = threadIdx.x;
    const int row = rhalf + (tid >> 2), colq = (tid & 3) * 16;
    const int base = ((b * H_ + h) * 4 + qt) * SPLIT;

    float m0 = g_PM[(base + 0) * 128 + row];
    float m1 = g_PM[(base + 1) * 128 + row];
    float l0 = g_PL[(base + 0) * 128 + row];
    float l1 = g_PL[(base + 1) * 128 + row];
    float M = fmaxf(m0, m1);
    float w0 = exp2f(m0 - M), w1 = exp2f(m1 - M);
    float inv = 1.f / (w0 * l0 + w1 * l1);
    w0 *= inv; w1 *= inv;

    const float* p0 = g_PO + ((size_t)(base + 0) * 128 + row) * 64 + colq;
    const float* p1 = g_PO + ((size_t)(base + 1) * 128 + row) * 64 + colq;
    float* op = g_O2 + ((size_t)(b * NLAT + qt * 128 + row)) * 1024 + h * DH_ + colq;
#pragma unroll
    for (int j = 0; j < 4; j++) {
        float4 u = *(const float4*)(p0 + 4 * j);
        float4 v = *(const float4*)(p1 + 4 * j);
        float4 acc = make_float4(w0 * u.x + w1 * v.x, w0 * u.y + w1 * v.y,
                                 w0 * u.z + w1 * v.z, w0 * u.w + w1 * v.w);
        float4 hi = make_float4(f2tf(acc.x), f2tf(acc.y), f2tf(acc.z), f2tf(acc.w));
        float4 lo = make_float4(f2tf(acc.x - hi.x), f2tf(acc.y - hi.y),
                                f2tf(acc.z - hi.z), f2tf(acc.w - hi.w));
        *(float4*)(op + 4 * j)       = hi;
        *(float4*)(op + 512 + 4 * j) = lo;
    }
}

// ===========================================================================
// Launch
// ===========================================================================
extern "C" void kernel_launch(void* const* d_in, const int* in_sizes, int n_in,
                              void* d_out, int out_size)
{
    const float* x    = (const float*)d_in[0];
    const float* ctx  = (const float*)d_in[1];
    const float* Wq   = (const float*)d_in[2];
    const float* Wkv  = (const float*)d_in[3];
    const float* Wout = (const float*)d_in[4];
    float* out = (float*)d_out;

    cudaFuncSetAttribute(gemm_fused, cudaFuncAttributeMaxDynamicSharedMemorySize, GEMM_SMEM);
    cudaFuncSetAttribute(attn_ca,    cudaFuncAttributeMaxDynamicSharedMemorySize, ATT_SMEM);

    // 0. round inputs to tf32 (+ fold scale into Wq, replicate Wout)
    prep_round<<<(unsigned)((NP4_TOT + 255) / 256), 256>>>(x, ctx, Wq, Wkv, Wout);

    // 1. KV-proj (K + pair-interleaved V2) fused with Q-proj
    gemm_fused<<<dim3(304, 1, B_), 256, GEMM_SMEM>>>(0, nullptr);

    // 2. attention partials (split-K by 2, single wave)
    attn_ca<<<dim3(NLAT / 128, H_, B_ * SPLIT), 256, ATT_SMEM>>>();

    // 3. merge partials -> O2 (hi|lo)
    merge_k<<<dim3(8, H_, B_), 256>>>();

    // 4. out = (Ohi + Olo) @ Wout^T  (K=1024 pipelined gemm)
    gemm_fused<<<dim3(DIM_ / 128, NLAT / 128, B_), 256, GEMM_SMEM>>>(1, out);
}